// round 2
// baseline (speedup 1.0000x reference)
#include <cuda_runtime.h>
#include <cuda_bf16.h>
#include <math.h>

#define DIM   1024
#define BATCH 2
#define SEQ   2048
#define NHEAD 16
#define HDIM  64
#define NTOK  (BATCH * SEQ)          // 4096
#define HID   (4 * DIM)              // 4096
#define ATTN_SCALE 0.125f            // 64^-0.5
#define LN_EPS 1e-5f

// ---------------------------------------------------------------------------
// Scratch (static device globals; no allocations allowed)
// ---------------------------------------------------------------------------
__device__ float g_nx  [NTOK * DIM];   // normalized activations (reused)
__device__ float g_q   [NTOK * DIM];
__device__ float g_k   [NTOK * DIM];
__device__ float g_v   [NTOK * DIM];
__device__ float g_attn[NTOK * DIM];   // attention output (pre out-proj)
__device__ float g_x1  [NTOK * DIM];   // x + attn_out
__device__ float g_h   [NTOK * HID];   // MLP hidden

// ---------------------------------------------------------------------------
// LayerNorm: one block per row of 1024 floats, 256 threads, float4 loads
// ---------------------------------------------------------------------------
__global__ __launch_bounds__(256) void ln_kernel(
    const float* __restrict__ x, const float* __restrict__ g,
    const float* __restrict__ b, float* __restrict__ y)
{
    int row = blockIdx.x;
    int tid = threadIdx.x;
    const float4* xr = reinterpret_cast<const float4*>(x + (size_t)row * DIM);
    float4 v = xr[tid];
    float s  = v.x + v.y + v.z + v.w;
    float sq = v.x*v.x + v.y*v.y + v.z*v.z + v.w*v.w;

    // warp reduce
    #pragma unroll
    for (int o = 16; o > 0; o >>= 1) {
        s  += __shfl_xor_sync(0xffffffffu, s,  o);
        sq += __shfl_xor_sync(0xffffffffu, sq, o);
    }
    __shared__ float rs[8], rq[8];
    int warp = tid >> 5, lane = tid & 31;
    if (lane == 0) { rs[warp] = s; rq[warp] = sq; }
    __syncthreads();
    if (warp == 0) {
        float a = (lane < 8) ? rs[lane] : 0.f;
        float c = (lane < 8) ? rq[lane] : 0.f;
        #pragma unroll
        for (int o = 4; o > 0; o >>= 1) {
            a += __shfl_xor_sync(0xffffffffu, a, o);
            c += __shfl_xor_sync(0xffffffffu, c, o);
        }
        if (lane == 0) { rs[0] = a; rq[0] = c; }
    }
    __syncthreads();
    float mean = rs[0] * (1.0f / DIM);
    float var  = rq[0] * (1.0f / DIM) - mean * mean;
    float inv  = rsqrtf(var + LN_EPS);

    float4 gv = reinterpret_cast<const float4*>(g)[tid];
    float4 bv = reinterpret_cast<const float4*>(b)[tid];
    float4 o;
    o.x = (v.x - mean) * inv * gv.x + bv.x;
    o.y = (v.y - mean) * inv * gv.y + bv.y;
    o.z = (v.z - mean) * inv * gv.z + bv.z;
    o.w = (v.w - mean) * inv * gv.w + bv.w;
    reinterpret_cast<float4*>(y + (size_t)row * DIM)[tid] = o;
}

// ---------------------------------------------------------------------------
// GEMM: Y[M,N] = A[M,K] @ W[N,K]^T  (+ epilogue)
// 128x128 tile, BK=8, 256 threads, 8x8 per thread.
// ---------------------------------------------------------------------------
#define EPI_NONE       0
#define EPI_RESID      1
#define EPI_BIAS_GELU  2
#define EPI_BIAS_RESID 3

__device__ __forceinline__ float gelu_exact(float x) {
    return 0.5f * x * (1.0f + erff(x * 0.70710678118654752f));
}

template<int EPI>
__global__ __launch_bounds__(256) void gemm_kernel(
    const float* __restrict__ A, const float* __restrict__ W,
    const float* __restrict__ bias, const float* __restrict__ resid,
    float* __restrict__ Y, int M, int N, int K)
{
    __shared__ float As[8][132];
    __shared__ float Bs[8][132];

    int tid = threadIdx.x;
    int bm = blockIdx.y * 128;
    int bn = blockIdx.x * 128;

    int lrow = tid >> 1;          // 0..127
    int lcol = (tid & 1) * 4;     // 0 or 4
    const float* Aptr = A + (size_t)(bm + lrow) * K + lcol;
    const float* Wptr = W + (size_t)(bn + lrow) * K + lcol;

    int tx = tid & 15, ty = tid >> 4;
    int rowb = ty * 8, colb = tx * 8;

    float acc[8][8];
    #pragma unroll
    for (int i = 0; i < 8; i++)
        #pragma unroll
        for (int j = 0; j < 8; j++) acc[i][j] = 0.f;

    for (int k0 = 0; k0 < K; k0 += 8) {
        float4 a4 = *reinterpret_cast<const float4*>(Aptr + k0);
        float4 b4 = *reinterpret_cast<const float4*>(Wptr + k0);
        __syncthreads();
        As[lcol + 0][lrow] = a4.x;
        As[lcol + 1][lrow] = a4.y;
        As[lcol + 2][lrow] = a4.z;
        As[lcol + 3][lrow] = a4.w;
        Bs[lcol + 0][lrow] = b4.x;
        Bs[lcol + 1][lrow] = b4.y;
        Bs[lcol + 2][lrow] = b4.z;
        Bs[lcol + 3][lrow] = b4.w;
        __syncthreads();

        #pragma unroll
        for (int kk = 0; kk < 8; kk++) {
            float4 a0 = *reinterpret_cast<const float4*>(&As[kk][rowb]);
            float4 a1 = *reinterpret_cast<const float4*>(&As[kk][rowb + 4]);
            float4 b0 = *reinterpret_cast<const float4*>(&Bs[kk][colb]);
            float4 b1 = *reinterpret_cast<const float4*>(&Bs[kk][colb + 4]);
            float ar[8] = {a0.x,a0.y,a0.z,a0.w,a1.x,a1.y,a1.z,a1.w};
            float br[8] = {b0.x,b0.y,b0.z,b0.w,b1.x,b1.y,b1.z,b1.w};
            #pragma unroll
            for (int i = 0; i < 8; i++)
                #pragma unroll
                for (int j = 0; j < 8; j++)
                    acc[i][j] = fmaf(ar[i], br[j], acc[i][j]);
        }
    }

    #pragma unroll
    for (int i = 0; i < 8; i++) {
        int row = bm + rowb + i;
        #pragma unroll
        for (int j = 0; j < 8; j++) {
            int col = bn + colb + j;
            float vv = acc[i][j];
            if (EPI == EPI_BIAS_GELU)  vv = gelu_exact(vv + bias[col]);
            if (EPI == EPI_BIAS_RESID) vv = vv + bias[col] + resid[(size_t)row * N + col];
            if (EPI == EPI_RESID)      vv = vv + resid[(size_t)row * N + col];
            Y[(size_t)row * N + col] = vv;
        }
    }
}

// ---------------------------------------------------------------------------
// Flash attention (causal + seq_mask), fp32.
// Grid: (SEQ/64 q-tiles, NHEAD, BATCH). Block: 256 threads (8 warps).
// Each warp owns 8 q-rows; K/V tiles of 32 keys; online softmax.
// Masked scores are exactly -10000.0f to match the reference numerics.
// Q is pre-scaled by ATTN_SCALE on load.
// ---------------------------------------------------------------------------
__global__ __launch_bounds__(256) void attn_kernel(
    const float* __restrict__ q, const float* __restrict__ k,
    const float* __restrict__ v, const unsigned char* __restrict__ seq_mask,
    float* __restrict__ out)
{
    __shared__ float Qs[64][64];
    __shared__ float Ks[32][65];
    __shared__ float Vs[32][65];

    int qt = blockIdx.x, h = blockIdx.y, b = blockIdx.z;
    int tid = threadIdx.x, warp = tid >> 5, lane = tid & 31;
    int q0 = qt * 64;
    int hoff = h * HDIM;

    // load + pre-scale Q tile
    for (int i = tid; i < 64 * 64; i += 256) {
        int r = i >> 6, c = i & 63;
        Qs[r][c] = q[((size_t)(b * SEQ + q0 + r)) * DIM + hoff + c] * ATTN_SCALE;
    }

    float m_r[8], l_r[8], acc0[8], acc1[8];
    #pragma unroll
    for (int r = 0; r < 8; r++) { m_r[r] = -1e30f; l_r[r] = 0.f; acc0[r] = 0.f; acc1[r] = 0.f; }

    int nkt = qt * 2 + 2;  // tiles needed to cover causal range
    for (int kt = 0; kt < nkt; kt++) {
        int k0 = kt * 32;
        __syncthreads();
        for (int i = tid; i < 32 * 64; i += 256) {
            int r = i >> 6, c = i & 63;
            size_t gi = ((size_t)(b * SEQ + k0 + r)) * DIM + hoff + c;
            Ks[r][c] = k[gi];
            Vs[r][c] = v[gi];
        }
        __syncthreads();

        int key = k0 + lane;
        bool key_masked = (seq_mask[b * SEQ + key] != 0);

        #pragma unroll
        for (int r = 0; r < 8; r++) {
            int qrow = q0 + warp * 8 + r;
            float s = 0.f;
            #pragma unroll
            for (int kk = 0; kk < 64; kk++)
                s = fmaf(Qs[warp * 8 + r][kk], Ks[lane][kk], s);
            if (key_masked || key > qrow) s = -10000.0f;

            // warp-wide max of s
            float mt = s;
            #pragma unroll
            for (int o = 16; o > 0; o >>= 1)
                mt = fmaxf(mt, __shfl_xor_sync(0xffffffffu, mt, o));
            float m_new = fmaxf(m_r[r], mt);
            float corr  = __expf(m_r[r] - m_new);
            float p     = __expf(s - m_new);
            float ps = p;
            #pragma unroll
            for (int o = 16; o > 0; o >>= 1)
                ps += __shfl_xor_sync(0xffffffffu, ps, o);
            l_r[r] = l_r[r] * corr + ps;
            m_r[r] = m_new;
            acc0[r] *= corr;
            acc1[r] *= corr;

            #pragma unroll
            for (int kk = 0; kk < 32; kk++) {
                float pk = __shfl_sync(0xffffffffu, p, kk);
                acc0[r] = fmaf(pk, Vs[kk][lane],      acc0[r]);
                acc1[r] = fmaf(pk, Vs[kk][lane + 32], acc1[r]);
            }
        }
    }

    #pragma unroll
    for (int r = 0; r < 8; r++) {
        int qrow = q0 + warp * 8 + r;
        float invl = 1.0f / l_r[r];
        size_t oi = ((size_t)(b * SEQ + qrow)) * DIM + hoff;
        out[oi + lane]      = acc0[r] * invl;
        out[oi + lane + 32] = acc1[r] * invl;
    }
}

// ---------------------------------------------------------------------------
// Launch
// ---------------------------------------------------------------------------
extern "C" void kernel_launch(void* const* d_in, const int* in_sizes, int n_in,
                              void* d_out, int out_size)
{
    const float*         x        = (const float*)d_in[0];
    const unsigned char* seq_mask = (const unsigned char*)d_in[1];
    const float*         wq       = (const float*)d_in[2];
    const float*         wk       = (const float*)d_in[3];
    const float*         wv       = (const float*)d_in[4];
    const float*         wo       = (const float*)d_in[5];
    const float*         g1       = (const float*)d_in[6];
    const float*         b1       = (const float*)d_in[7];
    const float*         g2       = (const float*)d_in[8];
    const float*         b2       = (const float*)d_in[9];
    const float*         w_mlp1   = (const float*)d_in[10];
    const float*         b_mlp1   = (const float*)d_in[11];
    const float*         w_mlp2   = (const float*)d_in[12];
    const float*         b_mlp2   = (const float*)d_in[13];
    float*               out      = (float*)d_out;

    float *nx, *qb, *kb, *vb, *attnb, *x1, *hb;
    cudaGetSymbolAddress((void**)&nx,    g_nx);
    cudaGetSymbolAddress((void**)&qb,    g_q);
    cudaGetSymbolAddress((void**)&kb,    g_k);
    cudaGetSymbolAddress((void**)&vb,    g_v);
    cudaGetSymbolAddress((void**)&attnb, g_attn);
    cudaGetSymbolAddress((void**)&x1,    g_x1);
    cudaGetSymbolAddress((void**)&hb,    g_h);

    dim3 blk(256);

    // 1. nx = LN(x; g1, b1)
    ln_kernel<<<NTOK, blk>>>(x, g1, b1, nx);

    // 2. q/k/v = nx @ w{q,k,v}^T
    dim3 gproj(DIM / 128, NTOK / 128);   // (8, 32)
    gemm_kernel<EPI_NONE><<<gproj, blk>>>(nx, wq, nullptr, nullptr, qb, NTOK, DIM, DIM);
    gemm_kernel<EPI_NONE><<<gproj, blk>>>(nx, wk, nullptr, nullptr, kb, NTOK, DIM, DIM);
    gemm_kernel<EPI_NONE><<<gproj, blk>>>(nx, wv, nullptr, nullptr, vb, NTOK, DIM, DIM);

    // 3. causal flash attention
    dim3 gattn(SEQ / 64, NHEAD, BATCH);
    attn_kernel<<<gattn, blk>>>(qb, kb, vb, seq_mask, attnb);

    // 4. x1 = x + attn @ wo^T
    gemm_kernel<EPI_RESID><<<gproj, blk>>>(attnb, wo, nullptr, x, x1, NTOK, DIM, DIM);

    // 5. nx = LN(x1; g2, b2)
    ln_kernel<<<NTOK, blk>>>(x1, g2, b2, nx);

    // 6. h = gelu(nx @ w_mlp1^T + b_mlp1)
    dim3 gmlp1(HID / 128, NTOK / 128);   // (32, 32)
    gemm_kernel<EPI_BIAS_GELU><<<gmlp1, blk>>>(nx, w_mlp1, b_mlp1, nullptr, hb, NTOK, HID, DIM);

    // 7. out = x1 + h @ w_mlp2^T + b_mlp2
    gemm_kernel<EPI_BIAS_RESID><<<gproj, blk>>>(hb, w_mlp2, b_mlp2, x1, out, NTOK, DIM, HID);
}

// round 4
// speedup vs baseline: 1.6824x; 1.6824x over previous
#include <cuda_runtime.h>
#include <cuda_bf16.h>
#include <math.h>
#include <stdint.h>

#define DIM   1024
#define BATCH 2
#define SEQ   2048
#define NHEAD 16
#define HDIM  64
#define NTOK  (BATCH * SEQ)          // 4096
#define HID   (4 * DIM)              // 4096
#define ATTN_SCALE 0.125f
#define LN_EPS 1e-5f

// ===========================================================================
// PTX helpers (sm_80-era features only: ldmatrix / mma.sync / cp.async)
// ===========================================================================
static __device__ __forceinline__ uint32_t smem_u32(const void* p) {
    uint32_t a;
    asm("{ .reg .u64 t; cvta.to.shared.u64 t, %1; cvt.u32.u64 %0, t; }"
        : "=r"(a) : "l"(p));
    return a;
}

#define LDSM4(r0, r1, r2, r3, addr) \
    asm volatile("ldmatrix.sync.aligned.m8n8.x4.shared.b16 {%0,%1,%2,%3}, [%4];" \
        : "=r"(r0), "=r"(r1), "=r"(r2), "=r"(r3) : "r"(addr))

#define MMA16816(d, a0, a1, a2, a3, b0, b1) \
    asm volatile("mma.sync.aligned.m16n8k16.row.col.f32.bf16.bf16.f32 " \
        "{%0,%1,%2,%3}, {%4,%5,%6,%7}, {%8,%9}, {%0,%1,%2,%3};" \
        : "+f"((d)[0]), "+f"((d)[1]), "+f"((d)[2]), "+f"((d)[3]) \
        : "r"(a0), "r"(a1), "r"(a2), "r"(a3), "r"(b0), "r"(b1))

#define CPA16(dst, src) \
    asm volatile("cp.async.cg.shared.global [%0], [%1], 16;" :: "r"(dst), "l"(src))
#define CP_COMMIT() asm volatile("cp.async.commit_group;")
template<int N> static __device__ __forceinline__ void cp_wait() {
    asm volatile("cp.async.wait_group %0;" :: "n"(N));
}

// ===========================================================================
// Scratch (static device globals)
// ===========================================================================
__device__ float g_nx  [NTOK * DIM];
__device__ float g_q   [NTOK * DIM];
__device__ float g_k   [NTOK * DIM];
__device__ float g_v   [NTOK * DIM];
__device__ float g_attn[NTOK * DIM];
__device__ float g_x1  [NTOK * DIM];
__device__ float g_h   [NTOK * HID];

__device__ __nv_bfloat16 g_nx_hi[NTOK * DIM],  g_nx_lo[NTOK * DIM];
__device__ __nv_bfloat16 g_at_hi[NTOK * DIM],  g_at_lo[NTOK * DIM];
__device__ __nv_bfloat16 g_h_hi [NTOK * HID],  g_h_lo [NTOK * HID];
__device__ __nv_bfloat16 g_wq_hi[DIM * DIM],   g_wq_lo[DIM * DIM];
__device__ __nv_bfloat16 g_wk_hi[DIM * DIM],   g_wk_lo[DIM * DIM];
__device__ __nv_bfloat16 g_wv_hi[DIM * DIM],   g_wv_lo[DIM * DIM];
__device__ __nv_bfloat16 g_wo_hi[DIM * DIM],   g_wo_lo[DIM * DIM];
__device__ __nv_bfloat16 g_m1_hi[HID * DIM],   g_m1_lo[HID * DIM];
__device__ __nv_bfloat16 g_m2_hi[DIM * HID],   g_m2_lo[DIM * HID];

// ===========================================================================
// fp32 -> bf16 hi/lo split
// ===========================================================================
__global__ __launch_bounds__(256) void split_kernel(
    const float* __restrict__ x, __nv_bfloat16* __restrict__ hi,
    __nv_bfloat16* __restrict__ lo)
{
    int i = (blockIdx.x * 256 + threadIdx.x) * 4;
    float4 v = *reinterpret_cast<const float4*>(x + i);
    __nv_bfloat16 h0 = __float2bfloat16(v.x);
    __nv_bfloat16 h1 = __float2bfloat16(v.y);
    __nv_bfloat16 h2 = __float2bfloat16(v.z);
    __nv_bfloat16 h3 = __float2bfloat16(v.w);
    __nv_bfloat16 l0 = __float2bfloat16(v.x - __bfloat162float(h0));
    __nv_bfloat16 l1 = __float2bfloat16(v.y - __bfloat162float(h1));
    __nv_bfloat16 l2 = __float2bfloat16(v.z - __bfloat162float(h2));
    __nv_bfloat16 l3 = __float2bfloat16(v.w - __bfloat162float(h3));
    __nv_bfloat162 p;
    p.x = h0; p.y = h1; *reinterpret_cast<__nv_bfloat162*>(hi + i)     = p;
    p.x = h2; p.y = h3; *reinterpret_cast<__nv_bfloat162*>(hi + i + 2) = p;
    p.x = l0; p.y = l1; *reinterpret_cast<__nv_bfloat162*>(lo + i)     = p;
    p.x = l2; p.y = l3; *reinterpret_cast<__nv_bfloat162*>(lo + i + 2) = p;
}

// ===========================================================================
// LayerNorm
// ===========================================================================
__global__ __launch_bounds__(256) void ln_kernel(
    const float* __restrict__ x, const float* __restrict__ g,
    const float* __restrict__ b, float* __restrict__ y)
{
    int row = blockIdx.x;
    int tid = threadIdx.x;
    const float4* xr = reinterpret_cast<const float4*>(x + (size_t)row * DIM);
    float4 v = xr[tid];
    float s  = v.x + v.y + v.z + v.w;
    float sq = v.x*v.x + v.y*v.y + v.z*v.z + v.w*v.w;
    #pragma unroll
    for (int o = 16; o > 0; o >>= 1) {
        s  += __shfl_xor_sync(0xffffffffu, s,  o);
        sq += __shfl_xor_sync(0xffffffffu, sq, o);
    }
    __shared__ float rs[8], rq[8];
    int warp = tid >> 5, lane = tid & 31;
    if (lane == 0) { rs[warp] = s; rq[warp] = sq; }
    __syncthreads();
    if (warp == 0) {
        float a = (lane < 8) ? rs[lane] : 0.f;
        float c = (lane < 8) ? rq[lane] : 0.f;
        #pragma unroll
        for (int o = 4; o > 0; o >>= 1) {
            a += __shfl_xor_sync(0xffffffffu, a, o);
            c += __shfl_xor_sync(0xffffffffu, c, o);
        }
        if (lane == 0) { rs[0] = a; rq[0] = c; }
    }
    __syncthreads();
    float mean = rs[0] * (1.0f / DIM);
    float var  = rq[0] * (1.0f / DIM) - mean * mean;
    float inv  = rsqrtf(var + LN_EPS);
    float4 gv = reinterpret_cast<const float4*>(g)[tid];
    float4 bv = reinterpret_cast<const float4*>(b)[tid];
    float4 o;
    o.x = (v.x - mean) * inv * gv.x + bv.x;
    o.y = (v.y - mean) * inv * gv.y + bv.y;
    o.z = (v.z - mean) * inv * gv.z + bv.z;
    o.w = (v.w - mean) * inv * gv.w + bv.w;
    reinterpret_cast<float4*>(y + (size_t)row * DIM)[tid] = o;
}

// ===========================================================================
// HMMA bf16 GEMM with hi/lo compensation.
// Y[M,N] = A[M,K] @ W[N,K]^T (+ epilogue)
// CTA tile 128x128, BK=32, 8 warps (each 32x64), cp.async double buffer.
// ===========================================================================
#define EPI_NONE       0
#define EPI_RESID      1
#define EPI_BIAS_GELU  2
#define EPI_BIAS_RESID 3

__device__ __forceinline__ float gelu_exact(float x) {
    return 0.5f * x * (1.0f + erff(x * 0.70710678118654752f));
}

// SMEM: rows of 32 bf16 padded to 40 (80 B stride, conflict-free)
#define ROWB      80
#define PLANE     (128 * ROWB)          // 10240 B
#define OFF_AHI   0
#define OFF_ALO   (PLANE)
#define OFF_BHI   (2 * PLANE)
#define OFF_BLO   (3 * PLANE)
#define BUF_SZ    (4 * PLANE)           // 40960 B
#define GEMM_SMEM (2 * BUF_SZ)          // 81920 B

template<int EPI>
__global__ __launch_bounds__(256, 1) void gemm_tc(
    const __nv_bfloat16* __restrict__ Ahi, const __nv_bfloat16* __restrict__ Alo,
    const __nv_bfloat16* __restrict__ Whi, const __nv_bfloat16* __restrict__ Wlo,
    const float* __restrict__ bias, const float* __restrict__ resid,
    float* __restrict__ Y, int M, int N, int K)
{
    extern __shared__ char smem[];
    const uint32_t sb = smem_u32(smem);
    const int tid  = threadIdx.x;
    const int lane = tid & 31;
    const int wid  = tid >> 5;
    const int bm = blockIdx.y * 128;
    const int bn = blockIdx.x * 128;
    const int wm = (wid & 3) * 32;      // warp M offset (32 rows)
    const int wn = (wid >> 2) * 64;     // warp N offset (64 cols)

    float acc[2][8][4];
    #pragma unroll
    for (int i = 0; i < 2; i++)
        #pragma unroll
        for (int j = 0; j < 8; j++)
            #pragma unroll
            for (int t = 0; t < 4; t++) acc[i][j][t] = 0.f;

    // per-thread cp.async source/dest (2 x 16B chunks per plane per chunk)
    // chunk g in [0,512): row = g>>2, colchunk = g&3
    const int g0r = tid >> 2,           g0c = tid & 3;
    const int g1r = (tid + 256) >> 2,   g1c = tid & 3;  // (tid+256)&3 == tid&3

    // ldmatrix invariant addressing
    const uint32_t a_row   = wm + (lane & 15);
    const uint32_t a_cbyte = (lane >> 4) * 16;              // k-half within k16
    const uint32_t b_row0  = wn + ((lane >> 4) & 1) * 8 + (lane & 7);
    const uint32_t b_cbyte = ((lane >> 3) & 1) * 16;

    const int NC = K >> 5;              // K/32 chunks

    // ---- producer helper (macro to keep cp.async flat) ----
#define LOAD_CHUNK(cidx, bufbase)                                              \
    do {                                                                       \
        const int _k0 = (cidx) << 5;                                           \
        {                                                                      \
            size_t s0 = (size_t)(bm + g0r) * K + _k0 + g0c * 8;                \
            size_t s1 = (size_t)(bm + g1r) * K + _k0 + g1c * 8;                \
            uint32_t d0 = (bufbase) + g0r * ROWB + g0c * 16;                   \
            uint32_t d1 = (bufbase) + g1r * ROWB + g1c * 16;                   \
            CPA16(d0 + OFF_AHI, Ahi + s0); CPA16(d1 + OFF_AHI, Ahi + s1);      \
            CPA16(d0 + OFF_ALO, Alo + s0); CPA16(d1 + OFF_ALO, Alo + s1);      \
        }                                                                      \
        {                                                                      \
            size_t s0 = (size_t)(bn + g0r) * K + _k0 + g0c * 8;                \
            size_t s1 = (size_t)(bn + g1r) * K + _k0 + g1c * 8;                \
            uint32_t d0 = (bufbase) + g0r * ROWB + g0c * 16;                   \
            uint32_t d1 = (bufbase) + g1r * ROWB + g1c * 16;                   \
            CPA16(d0 + OFF_BHI, Whi + s0); CPA16(d1 + OFF_BHI, Whi + s1);      \
            CPA16(d0 + OFF_BLO, Wlo + s0); CPA16(d1 + OFF_BLO, Wlo + s1);      \
        }                                                                      \
    } while (0)

    LOAD_CHUNK(0, sb);
    CP_COMMIT();

    for (int c = 0; c < NC; c++) {
        const uint32_t buf = sb + (uint32_t)(c & 1) * BUF_SZ;
        if (c + 1 < NC) {
            LOAD_CHUNK(c + 1, sb + (uint32_t)((c + 1) & 1) * BUF_SZ);
            CP_COMMIT();
            cp_wait<1>();
        } else {
            cp_wait<0>();
        }
        __syncthreads();

        #pragma unroll
        for (int k16 = 0; k16 < 2; k16++) {
            const uint32_t kb = k16 * 32;
            uint32_t ah[2][4], al[2][4], bh[4][4], bl[4][4];
            #pragma unroll
            for (int mi = 0; mi < 2; mi++) {
                uint32_t ad = buf + (a_row + mi * 16) * ROWB + kb + a_cbyte;
                LDSM4(ah[mi][0], ah[mi][1], ah[mi][2], ah[mi][3], ad + OFF_AHI);
                LDSM4(al[mi][0], al[mi][1], al[mi][2], al[mi][3], ad + OFF_ALO);
            }
            #pragma unroll
            for (int p = 0; p < 4; p++) {
                uint32_t bd = buf + (b_row0 + p * 16) * ROWB + kb + b_cbyte;
                LDSM4(bh[p][0], bh[p][1], bh[p][2], bh[p][3], bd + OFF_BHI);
                LDSM4(bl[p][0], bl[p][1], bl[p][2], bl[p][3], bd + OFF_BLO);
            }
            #pragma unroll
            for (int mi = 0; mi < 2; mi++) {
                #pragma unroll
                for (int j = 0; j < 8; j++) {
                    const int p = j >> 1, q = (j & 1) * 2;
                    MMA16816(acc[mi][j], ah[mi][0], ah[mi][1], ah[mi][2], ah[mi][3],
                             bh[p][q], bh[p][q + 1]);
                    MMA16816(acc[mi][j], ah[mi][0], ah[mi][1], ah[mi][2], ah[mi][3],
                             bl[p][q], bl[p][q + 1]);
                    MMA16816(acc[mi][j], al[mi][0], al[mi][1], al[mi][2], al[mi][3],
                             bh[p][q], bh[p][q + 1]);
                }
            }
        }
        __syncthreads();
    }
#undef LOAD_CHUNK

    // ---- epilogue: write fp32 accumulators with fused ops ----
    #pragma unroll
    for (int mi = 0; mi < 2; mi++) {
        const int r0 = bm + wm + mi * 16 + (lane >> 2);
        #pragma unroll
        for (int j = 0; j < 8; j++) {
            const int col = bn + wn + j * 8 + (lane & 3) * 2;
            float2 v0 = make_float2(acc[mi][j][0], acc[mi][j][1]);
            float2 v1 = make_float2(acc[mi][j][2], acc[mi][j][3]);
            if (EPI == EPI_BIAS_GELU) {
                float2 bb = *reinterpret_cast<const float2*>(bias + col);
                v0.x = gelu_exact(v0.x + bb.x);  v0.y = gelu_exact(v0.y + bb.y);
                v1.x = gelu_exact(v1.x + bb.x);  v1.y = gelu_exact(v1.y + bb.y);
            } else if (EPI == EPI_BIAS_RESID) {
                float2 bb = *reinterpret_cast<const float2*>(bias + col);
                float2 r0v = *reinterpret_cast<const float2*>(resid + (size_t)r0 * N + col);
                float2 r1v = *reinterpret_cast<const float2*>(resid + (size_t)(r0 + 8) * N + col);
                v0.x += bb.x + r0v.x;  v0.y += bb.y + r0v.y;
                v1.x += bb.x + r1v.x;  v1.y += bb.y + r1v.y;
            } else if (EPI == EPI_RESID) {
                float2 r0v = *reinterpret_cast<const float2*>(resid + (size_t)r0 * N + col);
                float2 r1v = *reinterpret_cast<const float2*>(resid + (size_t)(r0 + 8) * N + col);
                v0.x += r0v.x;  v0.y += r0v.y;
                v1.x += r1v.x;  v1.y += r1v.y;
            }
            *reinterpret_cast<float2*>(Y + (size_t)r0 * N + col)       = v0;
            *reinterpret_cast<float2*>(Y + (size_t)(r0 + 8) * N + col) = v1;
        }
    }
}

// ===========================================================================
// Flash attention (fp32 SIMT, unchanged)
// ===========================================================================
__global__ __launch_bounds__(256) void attn_kernel(
    const float* __restrict__ q, const float* __restrict__ k,
    const float* __restrict__ v, const unsigned char* __restrict__ seq_mask,
    float* __restrict__ out)
{
    __shared__ float Qs[64][64];
    __shared__ float Ks[32][65];
    __shared__ float Vs[32][65];

    int qt = blockIdx.x, h = blockIdx.y, b = blockIdx.z;
    int tid = threadIdx.x, warp = tid >> 5, lane = tid & 31;
    int q0 = qt * 64;
    int hoff = h * HDIM;

    for (int i = tid; i < 64 * 64; i += 256) {
        int r = i >> 6, c = i & 63;
        Qs[r][c] = q[((size_t)(b * SEQ + q0 + r)) * DIM + hoff + c] * ATTN_SCALE;
    }

    float m_r[8], l_r[8], acc0[8], acc1[8];
    #pragma unroll
    for (int r = 0; r < 8; r++) { m_r[r] = -1e30f; l_r[r] = 0.f; acc0[r] = 0.f; acc1[r] = 0.f; }

    int nkt = qt * 2 + 2;
    for (int kt = 0; kt < nkt; kt++) {
        int k0 = kt * 32;
        __syncthreads();
        for (int i = tid; i < 32 * 64; i += 256) {
            int r = i >> 6, c = i & 63;
            size_t gi = ((size_t)(b * SEQ + k0 + r)) * DIM + hoff + c;
            Ks[r][c] = k[gi];
            Vs[r][c] = v[gi];
        }
        __syncthreads();

        int key = k0 + lane;
        bool key_masked = (seq_mask[b * SEQ + key] != 0);

        #pragma unroll
        for (int r = 0; r < 8; r++) {
            int qrow = q0 + warp * 8 + r;
            float s = 0.f;
            #pragma unroll
            for (int kk = 0; kk < 64; kk++)
                s = fmaf(Qs[warp * 8 + r][kk], Ks[lane][kk], s);
            if (key_masked || key > qrow) s = -10000.0f;

            float mt = s;
            #pragma unroll
            for (int o = 16; o > 0; o >>= 1)
                mt = fmaxf(mt, __shfl_xor_sync(0xffffffffu, mt, o));
            float m_new = fmaxf(m_r[r], mt);
            float corr  = __expf(m_r[r] - m_new);
            float p     = __expf(s - m_new);
            float ps = p;
            #pragma unroll
            for (int o = 16; o > 0; o >>= 1)
                ps += __shfl_xor_sync(0xffffffffu, ps, o);
            l_r[r] = l_r[r] * corr + ps;
            m_r[r] = m_new;
            acc0[r] *= corr;
            acc1[r] *= corr;

            #pragma unroll
            for (int kk = 0; kk < 32; kk++) {
                float pk = __shfl_sync(0xffffffffu, p, kk);
                acc0[r] = fmaf(pk, Vs[kk][lane],      acc0[r]);
                acc1[r] = fmaf(pk, Vs[kk][lane + 32], acc1[r]);
            }
        }
    }

    #pragma unroll
    for (int r = 0; r < 8; r++) {
        int qrow = q0 + warp * 8 + r;
        float invl = 1.0f / l_r[r];
        size_t oi = ((size_t)(b * SEQ + qrow)) * DIM + hoff;
        out[oi + lane]      = acc0[r] * invl;
        out[oi + lane + 32] = acc1[r] * invl;
    }
}

// ===========================================================================
// Launch
// ===========================================================================
extern "C" void kernel_launch(void* const* d_in, const int* in_sizes, int n_in,
                              void* d_out, int out_size)
{
    const float*         x        = (const float*)d_in[0];
    const unsigned char* seq_mask = (const unsigned char*)d_in[1];
    const float*         wq       = (const float*)d_in[2];
    const float*         wk       = (const float*)d_in[3];
    const float*         wv       = (const float*)d_in[4];
    const float*         wo       = (const float*)d_in[5];
    const float*         g1       = (const float*)d_in[6];
    const float*         b1       = (const float*)d_in[7];
    const float*         g2       = (const float*)d_in[8];
    const float*         b2       = (const float*)d_in[9];
    const float*         w_mlp1   = (const float*)d_in[10];
    const float*         b_mlp1   = (const float*)d_in[11];
    const float*         w_mlp2   = (const float*)d_in[12];
    const float*         b_mlp2   = (const float*)d_in[13];
    float*               out      = (float*)d_out;

    float *nx, *qb, *kb, *vb, *attnb, *x1, *hb;
    cudaGetSymbolAddress((void**)&nx,    g_nx);
    cudaGetSymbolAddress((void**)&qb,    g_q);
    cudaGetSymbolAddress((void**)&kb,    g_k);
    cudaGetSymbolAddress((void**)&vb,    g_v);
    cudaGetSymbolAddress((void**)&attnb, g_attn);
    cudaGetSymbolAddress((void**)&x1,    g_x1);
    cudaGetSymbolAddress((void**)&hb,    g_h);

    __nv_bfloat16 *nxh,*nxl,*ath,*atl,*hh,*hl,*wqh,*wql,*wkh,*wkl,*wvh,*wvl,*woh,*wol,*m1h,*m1l,*m2h,*m2l;
    cudaGetSymbolAddress((void**)&nxh, g_nx_hi); cudaGetSymbolAddress((void**)&nxl, g_nx_lo);
    cudaGetSymbolAddress((void**)&ath, g_at_hi); cudaGetSymbolAddress((void**)&atl, g_at_lo);
    cudaGetSymbolAddress((void**)&hh,  g_h_hi);  cudaGetSymbolAddress((void**)&hl,  g_h_lo);
    cudaGetSymbolAddress((void**)&wqh, g_wq_hi); cudaGetSymbolAddress((void**)&wql, g_wq_lo);
    cudaGetSymbolAddress((void**)&wkh, g_wk_hi); cudaGetSymbolAddress((void**)&wkl, g_wk_lo);
    cudaGetSymbolAddress((void**)&wvh, g_wv_hi); cudaGetSymbolAddress((void**)&wvl, g_wv_lo);
    cudaGetSymbolAddress((void**)&woh, g_wo_hi); cudaGetSymbolAddress((void**)&wol, g_wo_lo);
    cudaGetSymbolAddress((void**)&m1h, g_m1_hi); cudaGetSymbolAddress((void**)&m1l, g_m1_lo);
    cudaGetSymbolAddress((void**)&m2h, g_m2_hi); cudaGetSymbolAddress((void**)&m2l, g_m2_lo);

    cudaFuncSetAttribute(gemm_tc<EPI_NONE>,       cudaFuncAttributeMaxDynamicSharedMemorySize, GEMM_SMEM);
    cudaFuncSetAttribute(gemm_tc<EPI_RESID>,      cudaFuncAttributeMaxDynamicSharedMemorySize, GEMM_SMEM);
    cudaFuncSetAttribute(gemm_tc<EPI_BIAS_GELU>,  cudaFuncAttributeMaxDynamicSharedMemorySize, GEMM_SMEM);
    cudaFuncSetAttribute(gemm_tc<EPI_BIAS_RESID>, cudaFuncAttributeMaxDynamicSharedMemorySize, GEMM_SMEM);

    dim3 blk(256);

    // weight splits (data-independent)
    split_kernel<<<DIM * DIM / 1024, blk>>>(wq,     wqh, wql);
    split_kernel<<<DIM * DIM / 1024, blk>>>(wk,     wkh, wkl);
    split_kernel<<<DIM * DIM / 1024, blk>>>(wv,     wvh, wvl);
    split_kernel<<<DIM * DIM / 1024, blk>>>(wo,     woh, wol);
    split_kernel<<<HID * DIM / 1024, blk>>>(w_mlp1, m1h, m1l);
    split_kernel<<<DIM * HID / 1024, blk>>>(w_mlp2, m2h, m2l);

    // 1. nx = LN(x)
    ln_kernel<<<NTOK, blk>>>(x, g1, b1, nx);
    split_kernel<<<NTOK * DIM / 1024, blk>>>(nx, nxh, nxl);

    // 2. q/k/v projections
    dim3 gproj(DIM / 128, NTOK / 128);     // (8, 32)
    gemm_tc<EPI_NONE><<<gproj, blk, GEMM_SMEM>>>(nxh, nxl, wqh, wql, nullptr, nullptr, qb, NTOK, DIM, DIM);
    gemm_tc<EPI_NONE><<<gproj, blk, GEMM_SMEM>>>(nxh, nxl, wkh, wkl, nullptr, nullptr, kb, NTOK, DIM, DIM);
    gemm_tc<EPI_NONE><<<gproj, blk, GEMM_SMEM>>>(nxh, nxl, wvh, wvl, nullptr, nullptr, vb, NTOK, DIM, DIM);

    // 3. attention
    dim3 gattn(SEQ / 64, NHEAD, BATCH);
    attn_kernel<<<gattn, blk>>>(qb, kb, vb, seq_mask, attnb);

    // 4. x1 = x + attn @ wo^T
    split_kernel<<<NTOK * DIM / 1024, blk>>>(attnb, ath, atl);
    gemm_tc<EPI_RESID><<<gproj, blk, GEMM_SMEM>>>(ath, atl, woh, wol, nullptr, x, x1, NTOK, DIM, DIM);

    // 5. nx = LN(x1)
    ln_kernel<<<NTOK, blk>>>(x1, g2, b2, nx);
    split_kernel<<<NTOK * DIM / 1024, blk>>>(nx, nxh, nxl);

    // 6. h = gelu(nx @ w_mlp1^T + b_mlp1)
    dim3 gmlp1(HID / 128, NTOK / 128);     // (32, 32)
    gemm_tc<EPI_BIAS_GELU><<<gmlp1, blk, GEMM_SMEM>>>(nxh, nxl, m1h, m1l, b_mlp1, nullptr, hb, NTOK, HID, DIM);

    // 7. out = x1 + h @ w_mlp2^T + b_mlp2
    split_kernel<<<NTOK * HID / 1024, blk>>>(hb, hh, hl);
    dim3 gmlp2(DIM / 128, NTOK / 128);     // (8, 32)
    gemm_tc<EPI_BIAS_RESID><<<gmlp2, blk, GEMM_SMEM>>>(hh, hl, m2h, m2l, b_mlp2, x1, out, NTOK, DIM, HID);
}

// round 5
// speedup vs baseline: 2.6938x; 1.6012x over previous
#include <cuda_runtime.h>
#include <cuda_bf16.h>
#include <math.h>
#include <stdint.h>

#define DIM   1024
#define BATCH 2
#define SEQ   2048
#define NHEAD 16
#define HDIM  64
#define NTOK  (BATCH * SEQ)          // 4096
#define HID   (4 * DIM)              // 4096
#define ATTN_SCALE 0.125f
#define LN_EPS 1e-5f

// ===========================================================================
// PTX helpers
// ===========================================================================
static __device__ __forceinline__ uint32_t smem_u32(const void* p) {
    uint32_t a;
    asm("{ .reg .u64 t; cvta.to.shared.u64 t, %1; cvt.u32.u64 %0, t; }"
        : "=r"(a) : "l"(p));
    return a;
}

#define LDSM4(r0, r1, r2, r3, addr) \
    asm volatile("ldmatrix.sync.aligned.m8n8.x4.shared.b16 {%0,%1,%2,%3}, [%4];" \
        : "=r"(r0), "=r"(r1), "=r"(r2), "=r"(r3) : "r"(addr))

#define LDSM4T(r0, r1, r2, r3, addr) \
    asm volatile("ldmatrix.sync.aligned.m8n8.x4.trans.shared.b16 {%0,%1,%2,%3}, [%4];" \
        : "=r"(r0), "=r"(r1), "=r"(r2), "=r"(r3) : "r"(addr))

#define MMA16816(d, a0, a1, a2, a3, b0, b1) \
    asm volatile("mma.sync.aligned.m16n8k16.row.col.f32.bf16.bf16.f32 " \
        "{%0,%1,%2,%3}, {%4,%5,%6,%7}, {%8,%9}, {%0,%1,%2,%3};" \
        : "+f"((d)[0]), "+f"((d)[1]), "+f"((d)[2]), "+f"((d)[3]) \
        : "r"(a0), "r"(a1), "r"(a2), "r"(a3), "r"(b0), "r"(b1))

#define CPA16(dst, src) \
    asm volatile("cp.async.cg.shared.global [%0], [%1], 16;" :: "r"(dst), "l"(src))
#define CPA4(dst, src) \
    asm volatile("cp.async.ca.shared.global [%0], [%1], 4;" :: "r"(dst), "l"(src))
#define CP_COMMIT() asm volatile("cp.async.commit_group;")
template<int N> static __device__ __forceinline__ void cp_wait() {
    asm volatile("cp.async.wait_group %0;" :: "n"(N));
}

static __device__ __forceinline__ uint32_t pack_bf16(float a, float b) {
    __nv_bfloat162 t = __floats2bfloat162_rn(a, b);   // x = a (low), y = b (high)
    return *reinterpret_cast<uint32_t*>(&t);
}

// ===========================================================================
// Scratch (static device globals)
// ===========================================================================
__device__ float g_x1 [NTOK * DIM];

__device__ __nv_bfloat16 g_nx_hi[NTOK * DIM],  g_nx_lo[NTOK * DIM];
__device__ __nv_bfloat16 g_q_hi [NTOK * DIM],  g_q_lo [NTOK * DIM];
__device__ __nv_bfloat16 g_k_hi [NTOK * DIM],  g_k_lo [NTOK * DIM];
__device__ __nv_bfloat16 g_v_hi [NTOK * DIM],  g_v_lo [NTOK * DIM];
__device__ __nv_bfloat16 g_at_hi[NTOK * DIM],  g_at_lo[NTOK * DIM];
__device__ __nv_bfloat16 g_h_hi [NTOK * HID],  g_h_lo [NTOK * HID];
__device__ __nv_bfloat16 g_wq_hi[DIM * DIM],   g_wq_lo[DIM * DIM];
__device__ __nv_bfloat16 g_wk_hi[DIM * DIM],   g_wk_lo[DIM * DIM];
__device__ __nv_bfloat16 g_wv_hi[DIM * DIM],   g_wv_lo[DIM * DIM];
__device__ __nv_bfloat16 g_wo_hi[DIM * DIM],   g_wo_lo[DIM * DIM];
__device__ __nv_bfloat16 g_m1_hi[HID * DIM],   g_m1_lo[HID * DIM];
__device__ __nv_bfloat16 g_m2_hi[DIM * HID],   g_m2_lo[DIM * HID];

// ===========================================================================
// fp32 -> bf16 hi/lo split (weights only now)
// ===========================================================================
__global__ __launch_bounds__(256) void split_kernel(
    const float* __restrict__ x, __nv_bfloat16* __restrict__ hi,
    __nv_bfloat16* __restrict__ lo)
{
    int i = (blockIdx.x * 256 + threadIdx.x) * 4;
    float4 v = *reinterpret_cast<const float4*>(x + i);
    __nv_bfloat16 h0 = __float2bfloat16(v.x);
    __nv_bfloat16 h1 = __float2bfloat16(v.y);
    __nv_bfloat16 h2 = __float2bfloat16(v.z);
    __nv_bfloat16 h3 = __float2bfloat16(v.w);
    __nv_bfloat16 l0 = __float2bfloat16(v.x - __bfloat162float(h0));
    __nv_bfloat16 l1 = __float2bfloat16(v.y - __bfloat162float(h1));
    __nv_bfloat16 l2 = __float2bfloat16(v.z - __bfloat162float(h2));
    __nv_bfloat16 l3 = __float2bfloat16(v.w - __bfloat162float(h3));
    __nv_bfloat162 p;
    p.x = h0; p.y = h1; *reinterpret_cast<__nv_bfloat162*>(hi + i)     = p;
    p.x = h2; p.y = h3; *reinterpret_cast<__nv_bfloat162*>(hi + i + 2) = p;
    p.x = l0; p.y = l1; *reinterpret_cast<__nv_bfloat162*>(lo + i)     = p;
    p.x = l2; p.y = l3; *reinterpret_cast<__nv_bfloat162*>(lo + i + 2) = p;
}

// ===========================================================================
// LayerNorm -> bf16 hi/lo
// ===========================================================================
__global__ __launch_bounds__(256) void ln_hilo_kernel(
    const float* __restrict__ x, const float* __restrict__ g,
    const float* __restrict__ b, __nv_bfloat16* __restrict__ yh,
    __nv_bfloat16* __restrict__ yl)
{
    int row = blockIdx.x;
    int tid = threadIdx.x;
    const float4* xr = reinterpret_cast<const float4*>(x + (size_t)row * DIM);
    float4 v = xr[tid];
    float s  = v.x + v.y + v.z + v.w;
    float sq = v.x*v.x + v.y*v.y + v.z*v.z + v.w*v.w;
    #pragma unroll
    for (int o = 16; o > 0; o >>= 1) {
        s  += __shfl_xor_sync(0xffffffffu, s,  o);
        sq += __shfl_xor_sync(0xffffffffu, sq, o);
    }
    __shared__ float rs[8], rq[8];
    int warp = tid >> 5, lane = tid & 31;
    if (lane == 0) { rs[warp] = s; rq[warp] = sq; }
    __syncthreads();
    if (warp == 0) {
        float a = (lane < 8) ? rs[lane] : 0.f;
        float c = (lane < 8) ? rq[lane] : 0.f;
        #pragma unroll
        for (int o = 4; o > 0; o >>= 1) {
            a += __shfl_xor_sync(0xffffffffu, a, o);
            c += __shfl_xor_sync(0xffffffffu, c, o);
        }
        if (lane == 0) { rs[0] = a; rq[0] = c; }
    }
    __syncthreads();
    float mean = rs[0] * (1.0f / DIM);
    float var  = rq[0] * (1.0f / DIM) - mean * mean;
    float inv  = rsqrtf(var + LN_EPS);
    float4 gv = reinterpret_cast<const float4*>(g)[tid];
    float4 bv = reinterpret_cast<const float4*>(b)[tid];
    float o0 = (v.x - mean) * inv * gv.x + bv.x;
    float o1 = (v.y - mean) * inv * gv.y + bv.y;
    float o2 = (v.z - mean) * inv * gv.z + bv.z;
    float o3 = (v.w - mean) * inv * gv.w + bv.w;
    size_t base = (size_t)row * DIM + tid * 4;
    __nv_bfloat162 h01 = __floats2bfloat162_rn(o0, o1);
    __nv_bfloat162 h23 = __floats2bfloat162_rn(o2, o3);
    __nv_bfloat162 l01 = __floats2bfloat162_rn(o0 - __bfloat162float(h01.x),
                                               o1 - __bfloat162float(h01.y));
    __nv_bfloat162 l23 = __floats2bfloat162_rn(o2 - __bfloat162float(h23.x),
                                               o3 - __bfloat162float(h23.y));
    *reinterpret_cast<__nv_bfloat162*>(yh + base)     = h01;
    *reinterpret_cast<__nv_bfloat162*>(yh + base + 2) = h23;
    *reinterpret_cast<__nv_bfloat162*>(yl + base)     = l01;
    *reinterpret_cast<__nv_bfloat162*>(yl + base + 2) = l23;
}

// ===========================================================================
// HMMA bf16 GEMM with hi/lo compensation + fused epilogues
// ===========================================================================
#define EPI_RESID      1
#define EPI_BIAS_RESID 3
#define EPI_HILO       4
#define EPI_GELU_HILO  5

__device__ __forceinline__ float gelu_exact(float x) {
    return 0.5f * x * (1.0f + erff(x * 0.70710678118654752f));
}

#define ROWB      80
#define PLANE     (128 * ROWB)
#define OFF_AHI   0
#define OFF_ALO   (PLANE)
#define OFF_BHI   (2 * PLANE)
#define OFF_BLO   (3 * PLANE)
#define BUF_SZ    (4 * PLANE)
#define GEMM_SMEM (2 * BUF_SZ)

template<int EPI>
__global__ __launch_bounds__(256, 1) void gemm_tc(
    const __nv_bfloat16* __restrict__ Ahi, const __nv_bfloat16* __restrict__ Alo,
    const __nv_bfloat16* __restrict__ Whi, const __nv_bfloat16* __restrict__ Wlo,
    const float* __restrict__ bias, const float* __restrict__ resid,
    float* __restrict__ Y, __nv_bfloat16* __restrict__ Yh,
    __nv_bfloat16* __restrict__ Yl, int M, int N, int K)
{
    extern __shared__ char smem[];
    const uint32_t sb = smem_u32(smem);
    const int tid  = threadIdx.x;
    const int lane = tid & 31;
    const int wid  = tid >> 5;
    const int bm = blockIdx.y * 128;
    const int bn = blockIdx.x * 128;
    const int wm = (wid & 3) * 32;
    const int wn = (wid >> 2) * 64;

    float acc[2][8][4];
    #pragma unroll
    for (int i = 0; i < 2; i++)
        #pragma unroll
        for (int j = 0; j < 8; j++)
            #pragma unroll
            for (int t = 0; t < 4; t++) acc[i][j][t] = 0.f;

    const int g0r = tid >> 2,         g0c = tid & 3;
    const int g1r = (tid + 256) >> 2, g1c = tid & 3;

    const uint32_t a_row   = wm + (lane & 15);
    const uint32_t a_cbyte = (lane >> 4) * 16;
    const uint32_t b_row0  = wn + ((lane >> 4) & 1) * 8 + (lane & 7);
    const uint32_t b_cbyte = ((lane >> 3) & 1) * 16;

    const int NC = K >> 5;

#define LOAD_CHUNK(cidx, bufbase)                                              \
    do {                                                                       \
        const int _k0 = (cidx) << 5;                                           \
        {                                                                      \
            size_t s0 = (size_t)(bm + g0r) * K + _k0 + g0c * 8;                \
            size_t s1 = (size_t)(bm + g1r) * K + _k0 + g1c * 8;                \
            uint32_t d0 = (bufbase) + g0r * ROWB + g0c * 16;                   \
            uint32_t d1 = (bufbase) + g1r * ROWB + g1c * 16;                   \
            CPA16(d0 + OFF_AHI, Ahi + s0); CPA16(d1 + OFF_AHI, Ahi + s1);      \
            CPA16(d0 + OFF_ALO, Alo + s0); CPA16(d1 + OFF_ALO, Alo + s1);      \
        }                                                                      \
        {                                                                      \
            size_t s0 = (size_t)(bn + g0r) * K + _k0 + g0c * 8;                \
            size_t s1 = (size_t)(bn + g1r) * K + _k0 + g1c * 8;                \
            uint32_t d0 = (bufbase) + g0r * ROWB + g0c * 16;                   \
            uint32_t d1 = (bufbase) + g1r * ROWB + g1c * 16;                   \
            CPA16(d0 + OFF_BHI, Whi + s0); CPA16(d1 + OFF_BHI, Whi + s1);      \
            CPA16(d0 + OFF_BLO, Wlo + s0); CPA16(d1 + OFF_BLO, Wlo + s1);      \
        }                                                                      \
    } while (0)

    LOAD_CHUNK(0, sb);
    CP_COMMIT();

    for (int c = 0; c < NC; c++) {
        const uint32_t buf = sb + (uint32_t)(c & 1) * BUF_SZ;
        if (c + 1 < NC) {
            LOAD_CHUNK(c + 1, sb + (uint32_t)((c + 1) & 1) * BUF_SZ);
            CP_COMMIT();
            cp_wait<1>();
        } else {
            cp_wait<0>();
        }
        __syncthreads();

        #pragma unroll
        for (int k16 = 0; k16 < 2; k16++) {
            const uint32_t kb = k16 * 32;
            uint32_t ah[2][4], al[2][4], bh[4][4], bl[4][4];
            #pragma unroll
            for (int mi = 0; mi < 2; mi++) {
                uint32_t ad = buf + (a_row + mi * 16) * ROWB + kb + a_cbyte;
                LDSM4(ah[mi][0], ah[mi][1], ah[mi][2], ah[mi][3], ad + OFF_AHI);
                LDSM4(al[mi][0], al[mi][1], al[mi][2], al[mi][3], ad + OFF_ALO);
            }
            #pragma unroll
            for (int p = 0; p < 4; p++) {
                uint32_t bd = buf + (b_row0 + p * 16) * ROWB + kb + b_cbyte;
                LDSM4(bh[p][0], bh[p][1], bh[p][2], bh[p][3], bd + OFF_BHI);
                LDSM4(bl[p][0], bl[p][1], bl[p][2], bl[p][3], bd + OFF_BLO);
            }
            #pragma unroll
            for (int mi = 0; mi < 2; mi++) {
                #pragma unroll
                for (int j = 0; j < 8; j++) {
                    const int p = j >> 1, q = (j & 1) * 2;
                    MMA16816(acc[mi][j], ah[mi][0], ah[mi][1], ah[mi][2], ah[mi][3],
                             bh[p][q], bh[p][q + 1]);
                    MMA16816(acc[mi][j], ah[mi][0], ah[mi][1], ah[mi][2], ah[mi][3],
                             bl[p][q], bl[p][q + 1]);
                    MMA16816(acc[mi][j], al[mi][0], al[mi][1], al[mi][2], al[mi][3],
                             bh[p][q], bh[p][q + 1]);
                }
            }
        }
        __syncthreads();
    }
#undef LOAD_CHUNK

    #pragma unroll
    for (int mi = 0; mi < 2; mi++) {
        const int r0 = bm + wm + mi * 16 + (lane >> 2);
        #pragma unroll
        for (int j = 0; j < 8; j++) {
            const int col = bn + wn + j * 8 + (lane & 3) * 2;
            float2 v0 = make_float2(acc[mi][j][0], acc[mi][j][1]);
            float2 v1 = make_float2(acc[mi][j][2], acc[mi][j][3]);
            if (EPI == EPI_GELU_HILO) {
                float2 bb = *reinterpret_cast<const float2*>(bias + col);
                v0.x = gelu_exact(v0.x + bb.x);  v0.y = gelu_exact(v0.y + bb.y);
                v1.x = gelu_exact(v1.x + bb.x);  v1.y = gelu_exact(v1.y + bb.y);
            } else if (EPI == EPI_BIAS_RESID) {
                float2 bb = *reinterpret_cast<const float2*>(bias + col);
                float2 r0v = *reinterpret_cast<const float2*>(resid + (size_t)r0 * N + col);
                float2 r1v = *reinterpret_cast<const float2*>(resid + (size_t)(r0 + 8) * N + col);
                v0.x += bb.x + r0v.x;  v0.y += bb.y + r0v.y;
                v1.x += bb.x + r1v.x;  v1.y += bb.y + r1v.y;
            } else if (EPI == EPI_RESID) {
                float2 r0v = *reinterpret_cast<const float2*>(resid + (size_t)r0 * N + col);
                float2 r1v = *reinterpret_cast<const float2*>(resid + (size_t)(r0 + 8) * N + col);
                v0.x += r0v.x;  v0.y += r0v.y;
                v1.x += r1v.x;  v1.y += r1v.y;
            }
            if (EPI == EPI_HILO || EPI == EPI_GELU_HILO) {
                __nv_bfloat162 h0 = __floats2bfloat162_rn(v0.x, v0.y);
                __nv_bfloat162 h1 = __floats2bfloat162_rn(v1.x, v1.y);
                __nv_bfloat162 l0 = __floats2bfloat162_rn(v0.x - __bfloat162float(h0.x),
                                                          v0.y - __bfloat162float(h0.y));
                __nv_bfloat162 l1 = __floats2bfloat162_rn(v1.x - __bfloat162float(h1.x),
                                                          v1.y - __bfloat162float(h1.y));
                *reinterpret_cast<__nv_bfloat162*>(Yh + (size_t)r0 * N + col)       = h0;
                *reinterpret_cast<__nv_bfloat162*>(Yh + (size_t)(r0 + 8) * N + col) = h1;
                *reinterpret_cast<__nv_bfloat162*>(Yl + (size_t)r0 * N + col)       = l0;
                *reinterpret_cast<__nv_bfloat162*>(Yl + (size_t)(r0 + 8) * N + col) = l1;
            } else {
                *reinterpret_cast<float2*>(Y + (size_t)r0 * N + col)       = v0;
                *reinterpret_cast<float2*>(Y + (size_t)(r0 + 8) * N + col) = v1;
            }
        }
    }
}

// ===========================================================================
// Flash attention on HMMA (hi/lo compensated) -> bf16 hi/lo output
// Grid: (SEQ/128, NHEAD, BATCH), 256 threads (8 warps x 16 q-rows).
// ===========================================================================
#define ASTRIDE   144                       // 64 bf16 = 128B + 16 pad
#define A_QH      0
#define A_QL      18432                     // 128*144
#define A_KV      36864
#define A_KVBUF   36864                     // per-buffer: KH,KL,VH,VL each 9216
#define A_PK      9216
#define A_MS      110592                    // 2 x 64 mask bytes
#define ATTN_SMEM 110720

__global__ __launch_bounds__(256, 1) void attn_tc(
    const __nv_bfloat16* __restrict__ qh, const __nv_bfloat16* __restrict__ ql,
    const __nv_bfloat16* __restrict__ kh, const __nv_bfloat16* __restrict__ kl,
    const __nv_bfloat16* __restrict__ vh, const __nv_bfloat16* __restrict__ vl,
    const unsigned char* __restrict__ seq_mask,
    __nv_bfloat16* __restrict__ oh, __nv_bfloat16* __restrict__ ol)
{
    extern __shared__ char smem[];
    const uint32_t sb = smem_u32(smem);
    const int qt = blockIdx.x, h = blockIdx.y, b = blockIdx.z;
    const int tid = threadIdx.x, warp = tid >> 5, lane = tid & 31;
    const int q0 = qt * 128;
    const int hoff = h * HDIM;

    // ---- prologue: async-load Q (hi/lo), then KV tile 0 ----
    #pragma unroll
    for (int p = 0; p < 8; p++) {
        const __nv_bfloat16* s = (p < 4) ? qh : ql;
        int idx = (p & 3) * 256 + tid;
        int row = idx >> 3, c = idx & 7;
        size_t src = (size_t)(b * SEQ + q0 + row) * DIM + hoff + c * 8;
        CPA16(sb + (uint32_t)(p >> 2) * 18432 + row * ASTRIDE + c * 16, s + src);
    }
    CP_COMMIT();

    const int nkt = 2 * qt + 2;

#define LOAD_KV(kt_, buf_)                                                     \
    do {                                                                       \
        const int _k0 = (kt_) * 64;                                            \
        const uint32_t bb = sb + A_KV + (uint32_t)(buf_) * A_KVBUF;            \
        _Pragma("unroll")                                                      \
        for (int p = 0; p < 8; p++) {                                          \
            const __nv_bfloat16* s = (p < 2) ? kh : (p < 4) ? kl               \
                                   : (p < 6) ? vh : vl;                        \
            int idx = (p & 1) * 256 + tid;                                     \
            int row = idx >> 3, c = idx & 7;                                   \
            size_t src = (size_t)(b * SEQ + _k0 + row) * DIM + hoff + c * 8;   \
            CPA16(bb + (uint32_t)(p >> 1) * A_PK + row * ASTRIDE + c * 16,     \
                  s + src);                                                    \
        }                                                                      \
        if (tid < 16)                                                          \
            CPA4(sb + A_MS + (uint32_t)(buf_) * 64 + tid * 4,                  \
                 seq_mask + b * SEQ + _k0 + tid * 4);                          \
    } while (0)

    LOAD_KV(0, 0);
    CP_COMMIT();
    cp_wait<1>();        // Q complete
    __syncthreads();

    // preload Q fragments (A operand, 4 k16 chunks of d=64)
    uint32_t qfh[4][4], qfl[4][4];
    {
        uint32_t abase = sb + (warp * 16 + (lane & 15)) * ASTRIDE + (lane >> 4) * 16;
        #pragma unroll
        for (int k16 = 0; k16 < 4; k16++) {
            LDSM4(qfh[k16][0], qfh[k16][1], qfh[k16][2], qfh[k16][3],
                  abase + A_QH + k16 * 32);
            LDSM4(qfl[k16][0], qfl[k16][1], qfl[k16][2], qfl[k16][3],
                  abase + A_QL + k16 * 32);
        }
    }

    float acco[8][4];
    #pragma unroll
    for (int j = 0; j < 8; j++)
        #pragma unroll
        for (int t = 0; t < 4; t++) acco[j][t] = 0.f;
    float m_lo = -1e30f, m_hi = -1e30f, l_lo = 0.f, l_hi = 0.f;

    const int qrow_lo = q0 + warp * 16 + (lane >> 2);
    const int qrow_hi = qrow_lo + 8;

    for (int kt = 0; kt < nkt; kt++) {
        cp_wait<0>();
        __syncthreads();
        if (kt + 1 < nkt) {
            LOAD_KV(kt + 1, (kt + 1) & 1);
            CP_COMMIT();
        }

        const int k0 = kt * 64;
        const uint32_t bufb = sb + A_KV + (uint32_t)(kt & 1) * A_KVBUF;
        const bool active = (k0 <= q0 + warp * 16 + 15);

        if (active) {
            // ---- S = Q @ K^T (3-term) ----
            float accs[8][4];
            #pragma unroll
            for (int j = 0; j < 8; j++)
                #pragma unroll
                for (int t = 0; t < 4; t++) accs[j][t] = 0.f;

            #pragma unroll
            for (int k16 = 0; k16 < 4; k16++) {
                #pragma unroll
                for (int g = 0; g < 4; g++) {
                    uint32_t kh4[4], kl4[4];
                    uint32_t bd = bufb + (g * 16 + ((lane >> 4) & 1) * 8 + (lane & 7)) * ASTRIDE
                                + ((lane >> 3) & 1) * 16 + k16 * 32;
                    LDSM4(kh4[0], kh4[1], kh4[2], kh4[3], bd);
                    LDSM4(kl4[0], kl4[1], kl4[2], kl4[3], bd + A_PK);
                    const int j0 = g * 2;
                    MMA16816(accs[j0], qfh[k16][0], qfh[k16][1], qfh[k16][2], qfh[k16][3], kh4[0], kh4[1]);
                    MMA16816(accs[j0], qfh[k16][0], qfh[k16][1], qfh[k16][2], qfh[k16][3], kl4[0], kl4[1]);
                    MMA16816(accs[j0], qfl[k16][0], qfl[k16][1], qfl[k16][2], qfl[k16][3], kh4[0], kh4[1]);
                    MMA16816(accs[j0+1], qfh[k16][0], qfh[k16][1], qfh[k16][2], qfh[k16][3], kh4[2], kh4[3]);
                    MMA16816(accs[j0+1], qfh[k16][0], qfh[k16][1], qfh[k16][2], qfh[k16][3], kl4[2], kl4[3]);
                    MMA16816(accs[j0+1], qfl[k16][0], qfl[k16][1], qfl[k16][2], qfl[k16][3], kh4[2], kh4[3]);
                }
            }

            // ---- scale + mask + online softmax ----
            const unsigned char* msk = (const unsigned char*)smem + A_MS + (kt & 1) * 64;
            const bool causal = (k0 + 63 > q0 + warp * 16);
            float rmax_lo = -1e30f, rmax_hi = -1e30f;
            #pragma unroll
            for (int j = 0; j < 8; j++) {
                int kloc = j * 8 + 2 * (lane & 3);
                int key0 = k0 + kloc;
                bool sm0 = msk[kloc] != 0, sm1 = msk[kloc + 1] != 0;
                float s0 = accs[j][0] * ATTN_SCALE, s1 = accs[j][1] * ATTN_SCALE;
                float s2 = accs[j][2] * ATTN_SCALE, s3 = accs[j][3] * ATTN_SCALE;
                if (sm0 || (causal && key0     > qrow_lo)) s0 = -10000.0f;
                if (sm1 || (causal && key0 + 1 > qrow_lo)) s1 = -10000.0f;
                if (sm0 || (causal && key0     > qrow_hi)) s2 = -10000.0f;
                if (sm1 || (causal && key0 + 1 > qrow_hi)) s3 = -10000.0f;
                accs[j][0] = s0; accs[j][1] = s1; accs[j][2] = s2; accs[j][3] = s3;
                rmax_lo = fmaxf(rmax_lo, fmaxf(s0, s1));
                rmax_hi = fmaxf(rmax_hi, fmaxf(s2, s3));
            }
            rmax_lo = fmaxf(rmax_lo, __shfl_xor_sync(0xffffffffu, rmax_lo, 1));
            rmax_lo = fmaxf(rmax_lo, __shfl_xor_sync(0xffffffffu, rmax_lo, 2));
            rmax_hi = fmaxf(rmax_hi, __shfl_xor_sync(0xffffffffu, rmax_hi, 1));
            rmax_hi = fmaxf(rmax_hi, __shfl_xor_sync(0xffffffffu, rmax_hi, 2));

            float mnew_lo = fmaxf(m_lo, rmax_lo), mnew_hi = fmaxf(m_hi, rmax_hi);
            float corr_lo = __expf(m_lo - mnew_lo), corr_hi = __expf(m_hi - mnew_hi);
            m_lo = mnew_lo; m_hi = mnew_hi;

            float sum_lo = 0.f, sum_hi = 0.f;
            #pragma unroll
            for (int j = 0; j < 8; j++) {
                float p0 = __expf(accs[j][0] - mnew_lo);
                float p1 = __expf(accs[j][1] - mnew_lo);
                float p2 = __expf(accs[j][2] - mnew_hi);
                float p3 = __expf(accs[j][3] - mnew_hi);
                accs[j][0] = p0; accs[j][1] = p1; accs[j][2] = p2; accs[j][3] = p3;
                sum_lo += p0 + p1;  sum_hi += p2 + p3;
            }
            sum_lo += __shfl_xor_sync(0xffffffffu, sum_lo, 1);
            sum_lo += __shfl_xor_sync(0xffffffffu, sum_lo, 2);
            sum_hi += __shfl_xor_sync(0xffffffffu, sum_hi, 1);
            sum_hi += __shfl_xor_sync(0xffffffffu, sum_hi, 2);
            l_lo = l_lo * corr_lo + sum_lo;
            l_hi = l_hi * corr_hi + sum_hi;
            #pragma unroll
            for (int j = 0; j < 8; j++) {
                acco[j][0] *= corr_lo; acco[j][1] *= corr_lo;
                acco[j][2] *= corr_hi; acco[j][3] *= corr_hi;
            }

            // ---- P -> bf16 hi/lo A-fragments ----
            uint32_t pfh[4][4], pfl[4][4];
            #pragma unroll
            for (int kk = 0; kk < 4; kk++) {
                const int j0 = kk * 2, j1 = kk * 2 + 1;
                pfh[kk][0] = pack_bf16(accs[j0][0], accs[j0][1]);
                pfh[kk][1] = pack_bf16(accs[j0][2], accs[j0][3]);
                pfh[kk][2] = pack_bf16(accs[j1][0], accs[j1][1]);
                pfh[kk][3] = pack_bf16(accs[j1][2], accs[j1][3]);
                __nv_bfloat162 h0 = *reinterpret_cast<__nv_bfloat162*>(&pfh[kk][0]);
                __nv_bfloat162 h1 = *reinterpret_cast<__nv_bfloat162*>(&pfh[kk][1]);
                __nv_bfloat162 h2 = *reinterpret_cast<__nv_bfloat162*>(&pfh[kk][2]);
                __nv_bfloat162 h3 = *reinterpret_cast<__nv_bfloat162*>(&pfh[kk][3]);
                pfl[kk][0] = pack_bf16(accs[j0][0] - __bfloat162float(h0.x),
                                       accs[j0][1] - __bfloat162float(h0.y));
                pfl[kk][1] = pack_bf16(accs[j0][2] - __bfloat162float(h1.x),
                                       accs[j0][3] - __bfloat162float(h1.y));
                pfl[kk][2] = pack_bf16(accs[j1][0] - __bfloat162float(h2.x),
                                       accs[j1][1] - __bfloat162float(h2.y));
                pfl[kk][3] = pack_bf16(accs[j1][2] - __bfloat162float(h3.x),
                                       accs[j1][3] - __bfloat162float(h3.y));
            }

            // ---- O += P @ V (3-term), V via ldmatrix.trans ----
            #pragma unroll
            for (int kk = 0; kk < 4; kk++) {
                #pragma unroll
                for (int g = 0; g < 4; g++) {
                    uint32_t vh4[4], vl4[4];
                    uint32_t vd = bufb + 2 * A_PK
                                + (kk * 16 + (lane & 7) + ((lane >> 3) & 1) * 8) * ASTRIDE
                                + g * 32 + ((lane >> 4) & 1) * 16;
                    LDSM4T(vh4[0], vh4[1], vh4[2], vh4[3], vd);
                    LDSM4T(vl4[0], vl4[1], vl4[2], vl4[3], vd + A_PK);
                    const int j0 = g * 2;
                    MMA16816(acco[j0], pfh[kk][0], pfh[kk][1], pfh[kk][2], pfh[kk][3], vh4[0], vh4[1]);
                    MMA16816(acco[j0], pfl[kk][0], pfl[kk][1], pfl[kk][2], pfl[kk][3], vh4[0], vh4[1]);
                    MMA16816(acco[j0], pfh[kk][0], pfh[kk][1], pfh[kk][2], pfh[kk][3], vl4[0], vl4[1]);
                    MMA16816(acco[j0+1], pfh[kk][0], pfh[kk][1], pfh[kk][2], pfh[kk][3], vh4[2], vh4[3]);
                    MMA16816(acco[j0+1], pfl[kk][0], pfl[kk][1], pfl[kk][2], pfl[kk][3], vh4[2], vh4[3]);
                    MMA16816(acco[j0+1], pfh[kk][0], pfh[kk][1], pfh[kk][2], pfh[kk][3], vl4[2], vl4[3]);
                }
            }
        }
        __syncthreads();
    }
#undef LOAD_KV

    // ---- finalize + write bf16 hi/lo ----
    const float inv_lo = 1.0f / l_lo, inv_hi = 1.0f / l_hi;
    const size_t row_lo = (size_t)(b * SEQ) + qrow_lo;
    const size_t row_hi = row_lo + 8;
    #pragma unroll
    for (int j = 0; j < 8; j++) {
        const int col = hoff + j * 8 + (lane & 3) * 2;
        float o0 = acco[j][0] * inv_lo, o1 = acco[j][1] * inv_lo;
        float o2 = acco[j][2] * inv_hi, o3 = acco[j][3] * inv_hi;
        __nv_bfloat162 h0 = __floats2bfloat162_rn(o0, o1);
        __nv_bfloat162 h1 = __floats2bfloat162_rn(o2, o3);
        __nv_bfloat162 l0 = __floats2bfloat162_rn(o0 - __bfloat162float(h0.x),
                                                  o1 - __bfloat162float(h0.y));
        __nv_bfloat162 l1 = __floats2bfloat162_rn(o2 - __bfloat162float(h1.x),
                                                  o3 - __bfloat162float(h1.y));
        *reinterpret_cast<__nv_bfloat162*>(oh + row_lo * DIM + col) = h0;
        *reinterpret_cast<__nv_bfloat162*>(oh + row_hi * DIM + col) = h1;
        *reinterpret_cast<__nv_bfloat162*>(ol + row_lo * DIM + col) = l0;
        *reinterpret_cast<__nv_bfloat162*>(ol + row_hi * DIM + col) = l1;
    }
}

// ===========================================================================
// Launch
// ===========================================================================
extern "C" void kernel_launch(void* const* d_in, const int* in_sizes, int n_in,
                              void* d_out, int out_size)
{
    const float*         x        = (const float*)d_in[0];
    const unsigned char* seq_mask = (const unsigned char*)d_in[1];
    const float*         wq       = (const float*)d_in[2];
    const float*         wk       = (const float*)d_in[3];
    const float*         wv       = (const float*)d_in[4];
    const float*         wo       = (const float*)d_in[5];
    const float*         g1       = (const float*)d_in[6];
    const float*         b1       = (const float*)d_in[7];
    const float*         g2       = (const float*)d_in[8];
    const float*         b2       = (const float*)d_in[9];
    const float*         w_mlp1   = (const float*)d_in[10];
    const float*         b_mlp1   = (const float*)d_in[11];
    const float*         w_mlp2   = (const float*)d_in[12];
    const float*         b_mlp2   = (const float*)d_in[13];
    float*               out      = (float*)d_out;

    float* x1;
    cudaGetSymbolAddress((void**)&x1, g_x1);

    __nv_bfloat16 *nxh,*nxl,*qh,*ql,*kh,*kl,*vh,*vl,*ath,*atl,*hh,*hl;
    __nv_bfloat16 *wqh,*wql,*wkh,*wkl,*wvh,*wvl,*woh,*wol,*m1h,*m1l,*m2h,*m2l;
    cudaGetSymbolAddress((void**)&nxh, g_nx_hi); cudaGetSymbolAddress((void**)&nxl, g_nx_lo);
    cudaGetSymbolAddress((void**)&qh,  g_q_hi);  cudaGetSymbolAddress((void**)&ql,  g_q_lo);
    cudaGetSymbolAddress((void**)&kh,  g_k_hi);  cudaGetSymbolAddress((void**)&kl,  g_k_lo);
    cudaGetSymbolAddress((void**)&vh,  g_v_hi);  cudaGetSymbolAddress((void**)&vl,  g_v_lo);
    cudaGetSymbolAddress((void**)&ath, g_at_hi); cudaGetSymbolAddress((void**)&atl, g_at_lo);
    cudaGetSymbolAddress((void**)&hh,  g_h_hi);  cudaGetSymbolAddress((void**)&hl,  g_h_lo);
    cudaGetSymbolAddress((void**)&wqh, g_wq_hi); cudaGetSymbolAddress((void**)&wql, g_wq_lo);
    cudaGetSymbolAddress((void**)&wkh, g_wk_hi); cudaGetSymbolAddress((void**)&wkl, g_wk_lo);
    cudaGetSymbolAddress((void**)&wvh, g_wv_hi); cudaGetSymbolAddress((void**)&wvl, g_wv_lo);
    cudaGetSymbolAddress((void**)&woh, g_wo_hi); cudaGetSymbolAddress((void**)&wol, g_wo_lo);
    cudaGetSymbolAddress((void**)&m1h, g_m1_hi); cudaGetSymbolAddress((void**)&m1l, g_m1_lo);
    cudaGetSymbolAddress((void**)&m2h, g_m2_hi); cudaGetSymbolAddress((void**)&m2l, g_m2_lo);

    cudaFuncSetAttribute(gemm_tc<EPI_RESID>,      cudaFuncAttributeMaxDynamicSharedMemorySize, GEMM_SMEM);
    cudaFuncSetAttribute(gemm_tc<EPI_BIAS_RESID>, cudaFuncAttributeMaxDynamicSharedMemorySize, GEMM_SMEM);
    cudaFuncSetAttribute(gemm_tc<EPI_HILO>,       cudaFuncAttributeMaxDynamicSharedMemorySize, GEMM_SMEM);
    cudaFuncSetAttribute(gemm_tc<EPI_GELU_HILO>,  cudaFuncAttributeMaxDynamicSharedMemorySize, GEMM_SMEM);
    cudaFuncSetAttribute(attn_tc,                 cudaFuncAttributeMaxDynamicSharedMemorySize, ATTN_SMEM);

    dim3 blk(256);

    // weight splits
    split_kernel<<<DIM * DIM / 1024, blk>>>(wq,     wqh, wql);
    split_kernel<<<DIM * DIM / 1024, blk>>>(wk,     wkh, wkl);
    split_kernel<<<DIM * DIM / 1024, blk>>>(wv,     wvh, wvl);
    split_kernel<<<DIM * DIM / 1024, blk>>>(wo,     woh, wol);
    split_kernel<<<HID * DIM / 1024, blk>>>(w_mlp1, m1h, m1l);
    split_kernel<<<DIM * HID / 1024, blk>>>(w_mlp2, m2h, m2l);

    // 1. nx = LN(x) -> hi/lo
    ln_hilo_kernel<<<NTOK, blk>>>(x, g1, b1, nxh, nxl);

    // 2. q/k/v projections -> hi/lo
    dim3 gproj(DIM / 128, NTOK / 128);
    gemm_tc<EPI_HILO><<<gproj, blk, GEMM_SMEM>>>(nxh, nxl, wqh, wql, nullptr, nullptr, nullptr, qh, ql, NTOK, DIM, DIM);
    gemm_tc<EPI_HILO><<<gproj, blk, GEMM_SMEM>>>(nxh, nxl, wkh, wkl, nullptr, nullptr, nullptr, kh, kl, NTOK, DIM, DIM);
    gemm_tc<EPI_HILO><<<gproj, blk, GEMM_SMEM>>>(nxh, nxl, wvh, wvl, nullptr, nullptr, nullptr, vh, vl, NTOK, DIM, DIM);

    // 3. flash attention (tensor cores) -> hi/lo
    dim3 gattn(SEQ / 128, NHEAD, BATCH);
    attn_tc<<<gattn, blk, ATTN_SMEM>>>(qh, ql, kh, kl, vh, vl, seq_mask, ath, atl);

    // 4. x1 = x + attn @ wo^T
    gemm_tc<EPI_RESID><<<gproj, blk, GEMM_SMEM>>>(ath, atl, woh, wol, nullptr, x, x1, nullptr, nullptr, NTOK, DIM, DIM);

    // 5. nx = LN(x1) -> hi/lo
    ln_hilo_kernel<<<NTOK, blk>>>(x1, g2, b2, nxh, nxl);

    // 6. h = gelu(nx @ w_mlp1^T + b_mlp1) -> hi/lo
    dim3 gmlp1(HID / 128, NTOK / 128);
    gemm_tc<EPI_GELU_HILO><<<gmlp1, blk, GEMM_SMEM>>>(nxh, nxl, m1h, m1l, b_mlp1, nullptr, nullptr, hh, hl, NTOK, HID, DIM);

    // 7. out = x1 + h @ w_mlp2^T + b_mlp2
    dim3 gmlp2(DIM / 128, NTOK / 128);
    gemm_tc<EPI_BIAS_RESID><<<gmlp2, blk, GEMM_SMEM>>>(hh, hl, m2h, m2l, b_mlp2, x1, out, nullptr, nullptr, NTOK, DIM, HID);
}

// round 6
// speedup vs baseline: 3.0265x; 1.1235x over previous
#include <cuda_runtime.h>
#include <cuda_bf16.h>
#include <math.h>
#include <stdint.h>

#define DIM   1024
#define BATCH 2
#define SEQ   2048
#define NHEAD 16
#define HDIM  64
#define NTOK  (BATCH * SEQ)          // 4096
#define HID   (4 * DIM)              // 4096
#define QKVS  (3 * DIM)              // 3072 fused qkv row stride
#define ATTN_SCALE 0.125f
#define LN_EPS 1e-5f

// ===========================================================================
// PTX helpers
// ===========================================================================
static __device__ __forceinline__ uint32_t smem_u32(const void* p) {
    uint32_t a;
    asm("{ .reg .u64 t; cvta.to.shared.u64 t, %1; cvt.u32.u64 %0, t; }"
        : "=r"(a) : "l"(p));
    return a;
}

#define LDSM4(r0, r1, r2, r3, addr) \
    asm volatile("ldmatrix.sync.aligned.m8n8.x4.shared.b16 {%0,%1,%2,%3}, [%4];" \
        : "=r"(r0), "=r"(r1), "=r"(r2), "=r"(r3) : "r"(addr))

#define LDSM4T(r0, r1, r2, r3, addr) \
    asm volatile("ldmatrix.sync.aligned.m8n8.x4.trans.shared.b16 {%0,%1,%2,%3}, [%4];" \
        : "=r"(r0), "=r"(r1), "=r"(r2), "=r"(r3) : "r"(addr))

#define MMA16816(d, a0, a1, a2, a3, b0, b1) \
    asm volatile("mma.sync.aligned.m16n8k16.row.col.f32.bf16.bf16.f32 " \
        "{%0,%1,%2,%3}, {%4,%5,%6,%7}, {%8,%9}, {%0,%1,%2,%3};" \
        : "+f"((d)[0]), "+f"((d)[1]), "+f"((d)[2]), "+f"((d)[3]) \
        : "r"(a0), "r"(a1), "r"(a2), "r"(a3), "r"(b0), "r"(b1))

#define CPA16(dst, src) \
    asm volatile("cp.async.cg.shared.global [%0], [%1], 16;" :: "r"(dst), "l"(src))
#define CPA4(dst, src) \
    asm volatile("cp.async.ca.shared.global [%0], [%1], 4;" :: "r"(dst), "l"(src))
#define CP_COMMIT() asm volatile("cp.async.commit_group;")
template<int N> static __device__ __forceinline__ void cp_wait() {
    asm volatile("cp.async.wait_group %0;" :: "n"(N));
}

static __device__ __forceinline__ uint32_t pack_bf16(float a, float b) {
    __nv_bfloat162 t = __floats2bfloat162_rn(a, b);
    return *reinterpret_cast<uint32_t*>(&t);
}

// ===========================================================================
// Scratch
// ===========================================================================
__device__ float g_x1 [NTOK * DIM];

__device__ __nv_bfloat16 g_nx_hi [NTOK * DIM],  g_nx_lo [NTOK * DIM];
__device__ __nv_bfloat16 g_qkv_hi[NTOK * QKVS], g_qkv_lo[NTOK * QKVS];
__device__ __nv_bfloat16 g_at_hi [NTOK * DIM],  g_at_lo [NTOK * DIM];
__device__ __nv_bfloat16 g_h_hi  [NTOK * HID],  g_h_lo  [NTOK * HID];
__device__ __nv_bfloat16 g_wqkv_hi[QKVS * DIM], g_wqkv_lo[QKVS * DIM];
__device__ __nv_bfloat16 g_wo_hi [DIM * DIM],   g_wo_lo [DIM * DIM];
__device__ __nv_bfloat16 g_m1_hi [HID * DIM],   g_m1_lo [HID * DIM];
__device__ __nv_bfloat16 g_m2_hi [DIM * HID],   g_m2_lo [DIM * HID];

// ===========================================================================
// fp32 -> bf16 hi/lo split (weights only)
// ===========================================================================
__global__ __launch_bounds__(256) void split_kernel(
    const float* __restrict__ x, __nv_bfloat16* __restrict__ hi,
    __nv_bfloat16* __restrict__ lo)
{
    int i = (blockIdx.x * 256 + threadIdx.x) * 4;
    float4 v = *reinterpret_cast<const float4*>(x + i);
    __nv_bfloat16 h0 = __float2bfloat16(v.x);
    __nv_bfloat16 h1 = __float2bfloat16(v.y);
    __nv_bfloat16 h2 = __float2bfloat16(v.z);
    __nv_bfloat16 h3 = __float2bfloat16(v.w);
    __nv_bfloat16 l0 = __float2bfloat16(v.x - __bfloat162float(h0));
    __nv_bfloat16 l1 = __float2bfloat16(v.y - __bfloat162float(h1));
    __nv_bfloat16 l2 = __float2bfloat16(v.z - __bfloat162float(h2));
    __nv_bfloat16 l3 = __float2bfloat16(v.w - __bfloat162float(h3));
    __nv_bfloat162 p;
    p.x = h0; p.y = h1; *reinterpret_cast<__nv_bfloat162*>(hi + i)     = p;
    p.x = h2; p.y = h3; *reinterpret_cast<__nv_bfloat162*>(hi + i + 2) = p;
    p.x = l0; p.y = l1; *reinterpret_cast<__nv_bfloat162*>(lo + i)     = p;
    p.x = l2; p.y = l3; *reinterpret_cast<__nv_bfloat162*>(lo + i + 2) = p;
}

// ===========================================================================
// LayerNorm -> bf16 hi/lo
// ===========================================================================
__global__ __launch_bounds__(256) void ln_hilo_kernel(
    const float* __restrict__ x, const float* __restrict__ g,
    const float* __restrict__ b, __nv_bfloat16* __restrict__ yh,
    __nv_bfloat16* __restrict__ yl)
{
    int row = blockIdx.x;
    int tid = threadIdx.x;
    const float4* xr = reinterpret_cast<const float4*>(x + (size_t)row * DIM);
    float4 v = xr[tid];
    float s  = v.x + v.y + v.z + v.w;
    float sq = v.x*v.x + v.y*v.y + v.z*v.z + v.w*v.w;
    #pragma unroll
    for (int o = 16; o > 0; o >>= 1) {
        s  += __shfl_xor_sync(0xffffffffu, s,  o);
        sq += __shfl_xor_sync(0xffffffffu, sq, o);
    }
    __shared__ float rs[8], rq[8];
    int warp = tid >> 5, lane = tid & 31;
    if (lane == 0) { rs[warp] = s; rq[warp] = sq; }
    __syncthreads();
    if (warp == 0) {
        float a = (lane < 8) ? rs[lane] : 0.f;
        float c = (lane < 8) ? rq[lane] : 0.f;
        #pragma unroll
        for (int o = 4; o > 0; o >>= 1) {
            a += __shfl_xor_sync(0xffffffffu, a, o);
            c += __shfl_xor_sync(0xffffffffu, c, o);
        }
        if (lane == 0) { rs[0] = a; rq[0] = c; }
    }
    __syncthreads();
    float mean = rs[0] * (1.0f / DIM);
    float var  = rq[0] * (1.0f / DIM) - mean * mean;
    float inv  = rsqrtf(var + LN_EPS);
    float4 gv = reinterpret_cast<const float4*>(g)[tid];
    float4 bv = reinterpret_cast<const float4*>(b)[tid];
    float o0 = (v.x - mean) * inv * gv.x + bv.x;
    float o1 = (v.y - mean) * inv * gv.y + bv.y;
    float o2 = (v.z - mean) * inv * gv.z + bv.z;
    float o3 = (v.w - mean) * inv * gv.w + bv.w;
    size_t base = (size_t)row * DIM + tid * 4;
    __nv_bfloat162 h01 = __floats2bfloat162_rn(o0, o1);
    __nv_bfloat162 h23 = __floats2bfloat162_rn(o2, o3);
    __nv_bfloat162 l01 = __floats2bfloat162_rn(o0 - __bfloat162float(h01.x),
                                               o1 - __bfloat162float(h01.y));
    __nv_bfloat162 l23 = __floats2bfloat162_rn(o2 - __bfloat162float(h23.x),
                                               o3 - __bfloat162float(h23.y));
    *reinterpret_cast<__nv_bfloat162*>(yh + base)     = h01;
    *reinterpret_cast<__nv_bfloat162*>(yh + base + 2) = h23;
    *reinterpret_cast<__nv_bfloat162*>(yl + base)     = l01;
    *reinterpret_cast<__nv_bfloat162*>(yl + base + 2) = l23;
}

// ===========================================================================
// HMMA bf16 GEMM, hi/lo compensated, occupancy 2
// ===========================================================================
#define EPI_RESID      1
#define EPI_BIAS_RESID 3
#define EPI_HILO       4
#define EPI_GELU_HILO  5

__device__ __forceinline__ float gelu_exact(float x) {
    return 0.5f * x * (1.0f + erff(x * 0.70710678118654752f));
}

#define ROWB      80
#define PLANE     (128 * ROWB)
#define OFF_AHI   0
#define OFF_ALO   (PLANE)
#define OFF_BHI   (2 * PLANE)
#define OFF_BLO   (3 * PLANE)
#define BUF_SZ    (4 * PLANE)
#define GEMM_SMEM (2 * BUF_SZ)      // 81920 B -> 2 CTAs/SM

template<int EPI>
__global__ __launch_bounds__(256, 2) void gemm_tc(
    const __nv_bfloat16* __restrict__ Ahi, const __nv_bfloat16* __restrict__ Alo,
    const __nv_bfloat16* __restrict__ Whi, const __nv_bfloat16* __restrict__ Wlo,
    const float* __restrict__ bias, const float* __restrict__ resid,
    float* __restrict__ Y, __nv_bfloat16* __restrict__ Yh,
    __nv_bfloat16* __restrict__ Yl, int M, int N, int K)
{
    extern __shared__ char smem[];
    const uint32_t sb = smem_u32(smem);
    const int tid  = threadIdx.x;
    const int lane = tid & 31;
    const int bm = blockIdx.y * 128;
    const int bn = blockIdx.x * 128;
    const int wid = tid >> 5;
    const int wm = (wid & 3) * 32;
    const int wn = (wid >> 2) * 64;

    float acc[2][8][4];
    #pragma unroll
    for (int i = 0; i < 2; i++)
        #pragma unroll
        for (int j = 0; j < 8; j++)
            #pragma unroll
            for (int t = 0; t < 4; t++) acc[i][j][t] = 0.f;

    const int g0r = tid >> 2,         g0c = tid & 3;
    const int g1r = (tid + 256) >> 2, g1c = tid & 3;

    const uint32_t a_row   = wm + (lane & 15);
    const uint32_t a_cbyte = (lane >> 4) * 16;
    const uint32_t b_row0  = wn + ((lane >> 4) & 1) * 8 + (lane & 7);
    const uint32_t b_cbyte = ((lane >> 3) & 1) * 16;

    const int NC = K >> 5;

#define LOAD_CHUNK(cidx, bufbase)                                              \
    do {                                                                       \
        const int _k0 = (cidx) << 5;                                           \
        {                                                                      \
            size_t s0 = (size_t)(bm + g0r) * K + _k0 + g0c * 8;                \
            size_t s1 = (size_t)(bm + g1r) * K + _k0 + g1c * 8;                \
            uint32_t d0 = (bufbase) + g0r * ROWB + g0c * 16;                   \
            uint32_t d1 = (bufbase) + g1r * ROWB + g1c * 16;                   \
            CPA16(d0 + OFF_AHI, Ahi + s0); CPA16(d1 + OFF_AHI, Ahi + s1);      \
            CPA16(d0 + OFF_ALO, Alo + s0); CPA16(d1 + OFF_ALO, Alo + s1);      \
        }                                                                      \
        {                                                                      \
            size_t s0 = (size_t)(bn + g0r) * K + _k0 + g0c * 8;                \
            size_t s1 = (size_t)(bn + g1r) * K + _k0 + g1c * 8;                \
            uint32_t d0 = (bufbase) + g0r * ROWB + g0c * 16;                   \
            uint32_t d1 = (bufbase) + g1r * ROWB + g1c * 16;                   \
            CPA16(d0 + OFF_BHI, Whi + s0); CPA16(d1 + OFF_BHI, Whi + s1);      \
            CPA16(d0 + OFF_BLO, Wlo + s0); CPA16(d1 + OFF_BLO, Wlo + s1);      \
        }                                                                      \
    } while (0)

    LOAD_CHUNK(0, sb);
    CP_COMMIT();

    for (int c = 0; c < NC; c++) {
        const uint32_t buf = sb + (uint32_t)(c & 1) * BUF_SZ;
        if (c + 1 < NC) {
            LOAD_CHUNK(c + 1, sb + (uint32_t)((c + 1) & 1) * BUF_SZ);
            CP_COMMIT();
            cp_wait<1>();
        } else {
            cp_wait<0>();
        }
        __syncthreads();

        #pragma unroll
        for (int k16 = 0; k16 < 2; k16++) {
            const uint32_t kb = k16 * 32;
            uint32_t ah[2][4], al[2][4];
            #pragma unroll
            for (int mi = 0; mi < 2; mi++) {
                uint32_t ad = buf + (a_row + mi * 16) * ROWB + kb + a_cbyte;
                LDSM4(ah[mi][0], ah[mi][1], ah[mi][2], ah[mi][3], ad + OFF_AHI);
                LDSM4(al[mi][0], al[mi][1], al[mi][2], al[mi][3], ad + OFF_ALO);
            }
            #pragma unroll
            for (int p = 0; p < 4; p++) {
                uint32_t bh4[4], bl4[4];
                uint32_t bd = buf + (b_row0 + p * 16) * ROWB + kb + b_cbyte;
                LDSM4(bh4[0], bh4[1], bh4[2], bh4[3], bd + OFF_BHI);
                LDSM4(bl4[0], bl4[1], bl4[2], bl4[3], bd + OFF_BLO);
                #pragma unroll
                for (int mi = 0; mi < 2; mi++) {
                    #pragma unroll
                    for (int jj = 0; jj < 2; jj++) {
                        const int j = p * 2 + jj, q = jj * 2;
                        MMA16816(acc[mi][j], ah[mi][0], ah[mi][1], ah[mi][2], ah[mi][3],
                                 bh4[q], bh4[q + 1]);
                        MMA16816(acc[mi][j], ah[mi][0], ah[mi][1], ah[mi][2], ah[mi][3],
                                 bl4[q], bl4[q + 1]);
                        MMA16816(acc[mi][j], al[mi][0], al[mi][1], al[mi][2], al[mi][3],
                                 bh4[q], bh4[q + 1]);
                    }
                }
            }
        }
        __syncthreads();
    }
#undef LOAD_CHUNK

    #pragma unroll
    for (int mi = 0; mi < 2; mi++) {
        const int r0 = bm + wm + mi * 16 + (lane >> 2);
        #pragma unroll
        for (int j = 0; j < 8; j++) {
            const int col = bn + wn + j * 8 + (lane & 3) * 2;
            float2 v0 = make_float2(acc[mi][j][0], acc[mi][j][1]);
            float2 v1 = make_float2(acc[mi][j][2], acc[mi][j][3]);
            if (EPI == EPI_GELU_HILO) {
                float2 bb = *reinterpret_cast<const float2*>(bias + col);
                v0.x = gelu_exact(v0.x + bb.x);  v0.y = gelu_exact(v0.y + bb.y);
                v1.x = gelu_exact(v1.x + bb.x);  v1.y = gelu_exact(v1.y + bb.y);
            } else if (EPI == EPI_BIAS_RESID) {
                float2 bb = *reinterpret_cast<const float2*>(bias + col);
                float2 r0v = *reinterpret_cast<const float2*>(resid + (size_t)r0 * N + col);
                float2 r1v = *reinterpret_cast<const float2*>(resid + (size_t)(r0 + 8) * N + col);
                v0.x += bb.x + r0v.x;  v0.y += bb.y + r0v.y;
                v1.x += bb.x + r1v.x;  v1.y += bb.y + r1v.y;
            } else if (EPI == EPI_RESID) {
                float2 r0v = *reinterpret_cast<const float2*>(resid + (size_t)r0 * N + col);
                float2 r1v = *reinterpret_cast<const float2*>(resid + (size_t)(r0 + 8) * N + col);
                v0.x += r0v.x;  v0.y += r0v.y;
                v1.x += r1v.x;  v1.y += r1v.y;
            }
            if (EPI == EPI_HILO || EPI == EPI_GELU_HILO) {
                __nv_bfloat162 h0 = __floats2bfloat162_rn(v0.x, v0.y);
                __nv_bfloat162 h1 = __floats2bfloat162_rn(v1.x, v1.y);
                __nv_bfloat162 l0 = __floats2bfloat162_rn(v0.x - __bfloat162float(h0.x),
                                                          v0.y - __bfloat162float(h0.y));
                __nv_bfloat162 l1 = __floats2bfloat162_rn(v1.x - __bfloat162float(h1.x),
                                                          v1.y - __bfloat162float(h1.y));
                *reinterpret_cast<__nv_bfloat162*>(Yh + (size_t)r0 * N + col)       = h0;
                *reinterpret_cast<__nv_bfloat162*>(Yh + (size_t)(r0 + 8) * N + col) = h1;
                *reinterpret_cast<__nv_bfloat162*>(Yl + (size_t)r0 * N + col)       = l0;
                *reinterpret_cast<__nv_bfloat162*>(Yl + (size_t)(r0 + 8) * N + col) = l1;
            } else {
                *reinterpret_cast<float2*>(Y + (size_t)r0 * N + col)       = v0;
                *reinterpret_cast<float2*>(Y + (size_t)(r0 + 8) * N + col) = v1;
            }
        }
    }
}

// ===========================================================================
// Flash attention on HMMA (reads fused qkv buffer, stride QKVS)
// ===========================================================================
#define ASTRIDE   144
#define A_QH      0
#define A_QL      18432
#define A_KV      36864
#define A_KVBUF   36864
#define A_PK      9216
#define A_MS      110592
#define ATTN_SMEM 110720

__global__ __launch_bounds__(256, 1) void attn_tc(
    const __nv_bfloat16* __restrict__ qkvh, const __nv_bfloat16* __restrict__ qkvl,
    const unsigned char* __restrict__ seq_mask,
    __nv_bfloat16* __restrict__ oh, __nv_bfloat16* __restrict__ ol)
{
    extern __shared__ char smem[];
    const uint32_t sb = smem_u32(smem);
    const int qt = blockIdx.x, h = blockIdx.y, b = blockIdx.z;
    const int tid = threadIdx.x, warp = tid >> 5, lane = tid & 31;
    const int q0 = qt * 128;
    const int hoff = h * HDIM;

    // Q tiles (hi/lo) from fused buffer (col offset 0)
    #pragma unroll
    for (int p = 0; p < 8; p++) {
        const __nv_bfloat16* s = (p < 4) ? qkvh : qkvl;
        int idx = (p & 3) * 256 + tid;
        int row = idx >> 3, c = idx & 7;
        size_t src = (size_t)(b * SEQ + q0 + row) * QKVS + hoff + c * 8;
        CPA16(sb + (uint32_t)(p >> 2) * 18432 + row * ASTRIDE + c * 16, s + src);
    }
    CP_COMMIT();

    const int nkt = 2 * qt + 2;

#define LOAD_KV(kt_, buf_)                                                     \
    do {                                                                       \
        const int _k0 = (kt_) * 64;                                            \
        const uint32_t bb = sb + A_KV + (uint32_t)(buf_) * A_KVBUF;            \
        _Pragma("unroll")                                                      \
        for (int p = 0; p < 8; p++) {                                          \
            const __nv_bfloat16* s = ((p & 2) == 0) ? qkvh : qkvl;             \
            const int colo = (p < 4) ? DIM : 2 * DIM;                          \
            int idx = (p & 1) * 256 + tid;                                     \
            int row = idx >> 3, c = idx & 7;                                   \
            size_t src = (size_t)(b * SEQ + _k0 + row) * QKVS + colo + hoff + c * 8; \
            const int plane = (p < 2) ? 0 : (p < 4) ? 1 : (p < 6) ? 2 : 3;     \
            CPA16(bb + (uint32_t)plane * A_PK + row * ASTRIDE + c * 16,        \
                  s + src);                                                    \
        }                                                                      \
        if (tid < 16)                                                          \
            CPA4(sb + A_MS + (uint32_t)(buf_) * 64 + tid * 4,                  \
                 seq_mask + b * SEQ + _k0 + tid * 4);                          \
    } while (0)

    LOAD_KV(0, 0);
    CP_COMMIT();
    cp_wait<1>();
    __syncthreads();

    uint32_t qfh[4][4], qfl[4][4];
    {
        uint32_t abase = sb + (warp * 16 + (lane & 15)) * ASTRIDE + (lane >> 4) * 16;
        #pragma unroll
        for (int k16 = 0; k16 < 4; k16++) {
            LDSM4(qfh[k16][0], qfh[k16][1], qfh[k16][2], qfh[k16][3],
                  abase + A_QH + k16 * 32);
            LDSM4(qfl[k16][0], qfl[k16][1], qfl[k16][2], qfl[k16][3],
                  abase + A_QL + k16 * 32);
        }
    }

    float acco[8][4];
    #pragma unroll
    for (int j = 0; j < 8; j++)
        #pragma unroll
        for (int t = 0; t < 4; t++) acco[j][t] = 0.f;
    float m_lo = -1e30f, m_hi = -1e30f, l_lo = 0.f, l_hi = 0.f;

    const int qrow_lo = q0 + warp * 16 + (lane >> 2);
    const int qrow_hi = qrow_lo + 8;

    for (int kt = 0; kt < nkt; kt++) {
        cp_wait<0>();
        __syncthreads();
        if (kt + 1 < nkt) {
            LOAD_KV(kt + 1, (kt + 1) & 1);
            CP_COMMIT();
        }

        const int k0 = kt * 64;
        const uint32_t bufb = sb + A_KV + (uint32_t)(kt & 1) * A_KVBUF;
        const bool active = (k0 <= q0 + warp * 16 + 15);

        if (active) {
            float accs[8][4];
            #pragma unroll
            for (int j = 0; j < 8; j++)
                #pragma unroll
                for (int t = 0; t < 4; t++) accs[j][t] = 0.f;

            #pragma unroll
            for (int k16 = 0; k16 < 4; k16++) {
                #pragma unroll
                for (int g = 0; g < 4; g++) {
                    uint32_t kh4[4], kl4[4];
                    uint32_t bd = bufb + (g * 16 + ((lane >> 4) & 1) * 8 + (lane & 7)) * ASTRIDE
                                + ((lane >> 3) & 1) * 16 + k16 * 32;
                    LDSM4(kh4[0], kh4[1], kh4[2], kh4[3], bd);
                    LDSM4(kl4[0], kl4[1], kl4[2], kl4[3], bd + A_PK);
                    const int j0 = g * 2;
                    MMA16816(accs[j0], qfh[k16][0], qfh[k16][1], qfh[k16][2], qfh[k16][3], kh4[0], kh4[1]);
                    MMA16816(accs[j0], qfh[k16][0], qfh[k16][1], qfh[k16][2], qfh[k16][3], kl4[0], kl4[1]);
                    MMA16816(accs[j0], qfl[k16][0], qfl[k16][1], qfl[k16][2], qfl[k16][3], kh4[0], kh4[1]);
                    MMA16816(accs[j0+1], qfh[k16][0], qfh[k16][1], qfh[k16][2], qfh[k16][3], kh4[2], kh4[3]);
                    MMA16816(accs[j0+1], qfh[k16][0], qfh[k16][1], qfh[k16][2], qfh[k16][3], kl4[2], kl4[3]);
                    MMA16816(accs[j0+1], qfl[k16][0], qfl[k16][1], qfl[k16][2], qfl[k16][3], kh4[2], kh4[3]);
                }
            }

            const unsigned char* msk = (const unsigned char*)smem + A_MS + (kt & 1) * 64;
            const bool causal = (k0 + 63 > q0 + warp * 16);
            float rmax_lo = -1e30f, rmax_hi = -1e30f;
            #pragma unroll
            for (int j = 0; j < 8; j++) {
                int kloc = j * 8 + 2 * (lane & 3);
                int key0 = k0 + kloc;
                bool sm0 = msk[kloc] != 0, sm1 = msk[kloc + 1] != 0;
                float s0 = accs[j][0] * ATTN_SCALE, s1 = accs[j][1] * ATTN_SCALE;
                float s2 = accs[j][2] * ATTN_SCALE, s3 = accs[j][3] * ATTN_SCALE;
                if (sm0 || (causal && key0     > qrow_lo)) s0 = -10000.0f;
                if (sm1 || (causal && key0 + 1 > qrow_lo)) s1 = -10000.0f;
                if (sm0 || (causal && key0     > qrow_hi)) s2 = -10000.0f;
                if (sm1 || (causal && key0 + 1 > qrow_hi)) s3 = -10000.0f;
                accs[j][0] = s0; accs[j][1] = s1; accs[j][2] = s2; accs[j][3] = s3;
                rmax_lo = fmaxf(rmax_lo, fmaxf(s0, s1));
                rmax_hi = fmaxf(rmax_hi, fmaxf(s2, s3));
            }
            rmax_lo = fmaxf(rmax_lo, __shfl_xor_sync(0xffffffffu, rmax_lo, 1));
            rmax_lo = fmaxf(rmax_lo, __shfl_xor_sync(0xffffffffu, rmax_lo, 2));
            rmax_hi = fmaxf(rmax_hi, __shfl_xor_sync(0xffffffffu, rmax_hi, 1));
            rmax_hi = fmaxf(rmax_hi, __shfl_xor_sync(0xffffffffu, rmax_hi, 2));

            float mnew_lo = fmaxf(m_lo, rmax_lo), mnew_hi = fmaxf(m_hi, rmax_hi);
            float corr_lo = __expf(m_lo - mnew_lo), corr_hi = __expf(m_hi - mnew_hi);
            m_lo = mnew_lo; m_hi = mnew_hi;

            float sum_lo = 0.f, sum_hi = 0.f;
            #pragma unroll
            for (int j = 0; j < 8; j++) {
                float p0 = __expf(accs[j][0] - mnew_lo);
                float p1 = __expf(accs[j][1] - mnew_lo);
                float p2 = __expf(accs[j][2] - mnew_hi);
                float p3 = __expf(accs[j][3] - mnew_hi);
                accs[j][0] = p0; accs[j][1] = p1; accs[j][2] = p2; accs[j][3] = p3;
                sum_lo += p0 + p1;  sum_hi += p2 + p3;
            }
            sum_lo += __shfl_xor_sync(0xffffffffu, sum_lo, 1);
            sum_lo += __shfl_xor_sync(0xffffffffu, sum_lo, 2);
            sum_hi += __shfl_xor_sync(0xffffffffu, sum_hi, 1);
            sum_hi += __shfl_xor_sync(0xffffffffu, sum_hi, 2);
            l_lo = l_lo * corr_lo + sum_lo;
            l_hi = l_hi * corr_hi + sum_hi;
            #pragma unroll
            for (int j = 0; j < 8; j++) {
                acco[j][0] *= corr_lo; acco[j][1] *= corr_lo;
                acco[j][2] *= corr_hi; acco[j][3] *= corr_hi;
            }

            uint32_t pfh[4][4], pfl[4][4];
            #pragma unroll
            for (int kk = 0; kk < 4; kk++) {
                const int j0 = kk * 2, j1 = kk * 2 + 1;
                pfh[kk][0] = pack_bf16(accs[j0][0], accs[j0][1]);
                pfh[kk][1] = pack_bf16(accs[j0][2], accs[j0][3]);
                pfh[kk][2] = pack_bf16(accs[j1][0], accs[j1][1]);
                pfh[kk][3] = pack_bf16(accs[j1][2], accs[j1][3]);
                __nv_bfloat162 h0 = *reinterpret_cast<__nv_bfloat162*>(&pfh[kk][0]);
                __nv_bfloat162 h1 = *reinterpret_cast<__nv_bfloat162*>(&pfh[kk][1]);
                __nv_bfloat162 h2 = *reinterpret_cast<__nv_bfloat162*>(&pfh[kk][2]);
                __nv_bfloat162 h3 = *reinterpret_cast<__nv_bfloat162*>(&pfh[kk][3]);
                pfl[kk][0] = pack_bf16(accs[j0][0] - __bfloat162float(h0.x),
                                       accs[j0][1] - __bfloat162float(h0.y));
                pfl[kk][1] = pack_bf16(accs[j0][2] - __bfloat162float(h1.x),
                                       accs[j0][3] - __bfloat162float(h1.y));
                pfl[kk][2] = pack_bf16(accs[j1][0] - __bfloat162float(h2.x),
                                       accs[j1][1] - __bfloat162float(h2.y));
                pfl[kk][3] = pack_bf16(accs[j1][2] - __bfloat162float(h3.x),
                                       accs[j1][3] - __bfloat162float(h3.y));
            }

            #pragma unroll
            for (int kk = 0; kk < 4; kk++) {
                #pragma unroll
                for (int g = 0; g < 4; g++) {
                    uint32_t vh4[4], vl4[4];
                    uint32_t vd = bufb + 2 * A_PK
                                + (kk * 16 + (lane & 7) + ((lane >> 3) & 1) * 8) * ASTRIDE
                                + g * 32 + ((lane >> 4) & 1) * 16;
                    LDSM4T(vh4[0], vh4[1], vh4[2], vh4[3], vd);
                    LDSM4T(vl4[0], vl4[1], vl4[2], vl4[3], vd + A_PK);
                    const int j0 = g * 2;
                    MMA16816(acco[j0], pfh[kk][0], pfh[kk][1], pfh[kk][2], pfh[kk][3], vh4[0], vh4[1]);
                    MMA16816(acco[j0], pfl[kk][0], pfl[kk][1], pfl[kk][2], pfl[kk][3], vh4[0], vh4[1]);
                    MMA16816(acco[j0], pfh[kk][0], pfh[kk][1], pfh[kk][2], pfh[kk][3], vl4[0], vl4[1]);
                    MMA16816(acco[j0+1], pfh[kk][0], pfh[kk][1], pfh[kk][2], pfh[kk][3], vh4[2], vh4[3]);
                    MMA16816(acco[j0+1], pfl[kk][0], pfl[kk][1], pfl[kk][2], pfl[kk][3], vh4[2], vh4[3]);
                    MMA16816(acco[j0+1], pfh[kk][0], pfh[kk][1], pfh[kk][2], pfh[kk][3], vl4[2], vl4[3]);
                }
            }
        }
        __syncthreads();
    }
#undef LOAD_KV

    const float inv_lo = 1.0f / l_lo, inv_hi = 1.0f / l_hi;
    const size_t row_lo = (size_t)(b * SEQ) + qrow_lo;
    const size_t row_hi = row_lo + 8;
    #pragma unroll
    for (int j = 0; j < 8; j++) {
        const int col = hoff + j * 8 + (lane & 3) * 2;
        float o0 = acco[j][0] * inv_lo, o1 = acco[j][1] * inv_lo;
        float o2 = acco[j][2] * inv_hi, o3 = acco[j][3] * inv_hi;
        __nv_bfloat162 h0 = __floats2bfloat162_rn(o0, o1);
        __nv_bfloat162 h1 = __floats2bfloat162_rn(o2, o3);
        __nv_bfloat162 l0 = __floats2bfloat162_rn(o0 - __bfloat162float(h0.x),
                                                  o1 - __bfloat162float(h0.y));
        __nv_bfloat162 l1 = __floats2bfloat162_rn(o2 - __bfloat162float(h1.x),
                                                  o3 - __bfloat162float(h1.y));
        *reinterpret_cast<__nv_bfloat162*>(oh + row_lo * DIM + col) = h0;
        *reinterpret_cast<__nv_bfloat162*>(oh + row_hi * DIM + col) = h1;
        *reinterpret_cast<__nv_bfloat162*>(ol + row_lo * DIM + col) = l0;
        *reinterpret_cast<__nv_bfloat162*>(ol + row_hi * DIM + col) = l1;
    }
}

// ===========================================================================
// Launch
// ===========================================================================
extern "C" void kernel_launch(void* const* d_in, const int* in_sizes, int n_in,
                              void* d_out, int out_size)
{
    const float*         x        = (const float*)d_in[0];
    const unsigned char* seq_mask = (const unsigned char*)d_in[1];
    const float*         wq       = (const float*)d_in[2];
    const float*         wk       = (const float*)d_in[3];
    const float*         wv       = (const float*)d_in[4];
    const float*         wo       = (const float*)d_in[5];
    const float*         g1       = (const float*)d_in[6];
    const float*         b1       = (const float*)d_in[7];
    const float*         g2       = (const float*)d_in[8];
    const float*         b2       = (const float*)d_in[9];
    const float*         w_mlp1   = (const float*)d_in[10];
    const float*         b_mlp1   = (const float*)d_in[11];
    const float*         w_mlp2   = (const float*)d_in[12];
    const float*         b_mlp2   = (const float*)d_in[13];
    float*               out      = (float*)d_out;

    float* x1;
    cudaGetSymbolAddress((void**)&x1, g_x1);

    __nv_bfloat16 *nxh,*nxl,*qkvh,*qkvl,*ath,*atl,*hh,*hl;
    __nv_bfloat16 *wqkvh,*wqkvl,*woh,*wol,*m1h,*m1l,*m2h,*m2l;
    cudaGetSymbolAddress((void**)&nxh,   g_nx_hi);  cudaGetSymbolAddress((void**)&nxl,   g_nx_lo);
    cudaGetSymbolAddress((void**)&qkvh,  g_qkv_hi); cudaGetSymbolAddress((void**)&qkvl,  g_qkv_lo);
    cudaGetSymbolAddress((void**)&ath,   g_at_hi);  cudaGetSymbolAddress((void**)&atl,   g_at_lo);
    cudaGetSymbolAddress((void**)&hh,    g_h_hi);   cudaGetSymbolAddress((void**)&hl,    g_h_lo);
    cudaGetSymbolAddress((void**)&wqkvh, g_wqkv_hi);cudaGetSymbolAddress((void**)&wqkvl, g_wqkv_lo);
    cudaGetSymbolAddress((void**)&woh,   g_wo_hi);  cudaGetSymbolAddress((void**)&wol,   g_wo_lo);
    cudaGetSymbolAddress((void**)&m1h,   g_m1_hi);  cudaGetSymbolAddress((void**)&m1l,   g_m1_lo);
    cudaGetSymbolAddress((void**)&m2h,   g_m2_hi);  cudaGetSymbolAddress((void**)&m2l,   g_m2_lo);

    cudaFuncSetAttribute(gemm_tc<EPI_RESID>,      cudaFuncAttributeMaxDynamicSharedMemorySize, GEMM_SMEM);
    cudaFuncSetAttribute(gemm_tc<EPI_BIAS_RESID>, cudaFuncAttributeMaxDynamicSharedMemorySize, GEMM_SMEM);
    cudaFuncSetAttribute(gemm_tc<EPI_HILO>,       cudaFuncAttributeMaxDynamicSharedMemorySize, GEMM_SMEM);
    cudaFuncSetAttribute(gemm_tc<EPI_GELU_HILO>,  cudaFuncAttributeMaxDynamicSharedMemorySize, GEMM_SMEM);
    cudaFuncSetAttribute(attn_tc,                 cudaFuncAttributeMaxDynamicSharedMemorySize, ATTN_SMEM);

    dim3 blk(256);

    // weight splits (qkv into fused [3*DIM, DIM] layout)
    split_kernel<<<DIM * DIM / 1024, blk>>>(wq,     wqkvh,                 wqkvl);
    split_kernel<<<DIM * DIM / 1024, blk>>>(wk,     wqkvh + DIM * DIM,     wqkvl + DIM * DIM);
    split_kernel<<<DIM * DIM / 1024, blk>>>(wv,     wqkvh + 2 * DIM * DIM, wqkvl + 2 * DIM * DIM);
    split_kernel<<<DIM * DIM / 1024, blk>>>(wo,     woh, wol);
    split_kernel<<<HID * DIM / 1024, blk>>>(w_mlp1, m1h, m1l);
    split_kernel<<<DIM * HID / 1024, blk>>>(w_mlp2, m2h, m2l);

    // 1. nx = LN(x) -> hi/lo
    ln_hilo_kernel<<<NTOK, blk>>>(x, g1, b1, nxh, nxl);

    // 2. fused qkv projection -> hi/lo (N = 3072)
    dim3 gqkv(QKVS / 128, NTOK / 128);   // (24, 32)
    gemm_tc<EPI_HILO><<<gqkv, blk, GEMM_SMEM>>>(nxh, nxl, wqkvh, wqkvl, nullptr, nullptr, nullptr, qkvh, qkvl, NTOK, QKVS, DIM);

    // 3. flash attention -> hi/lo
    dim3 gattn(SEQ / 128, NHEAD, BATCH);
    attn_tc<<<gattn, blk, ATTN_SMEM>>>(qkvh, qkvl, seq_mask, ath, atl);

    // 4. x1 = x + attn @ wo^T
    dim3 gproj(DIM / 128, NTOK / 128);
    gemm_tc<EPI_RESID><<<gproj, blk, GEMM_SMEM>>>(ath, atl, woh, wol, nullptr, x, x1, nullptr, nullptr, NTOK, DIM, DIM);

    // 5. nx = LN(x1) -> hi/lo
    ln_hilo_kernel<<<NTOK, blk>>>(x1, g2, b2, nxh, nxl);

    // 6. h = gelu(nx @ w_mlp1^T + b_mlp1) -> hi/lo
    dim3 gmlp1(HID / 128, NTOK / 128);
    gemm_tc<EPI_GELU_HILO><<<gmlp1, blk, GEMM_SMEM>>>(nxh, nxl, m1h, m1l, b_mlp1, nullptr, nullptr, hh, hl, NTOK, HID, DIM);

    // 7. out = x1 + h @ w_mlp2^T + b_mlp2
    dim3 gmlp2(DIM / 128, NTOK / 128);
    gemm_tc<EPI_BIAS_RESID><<<gmlp2, blk, GEMM_SMEM>>>(hh, hl, m2h, m2l, b_mlp2, x1, out, nullptr, nullptr, NTOK, DIM, HID);
}